// round 1
// baseline (speedup 1.0000x reference)
#include <cuda_runtime.h>
#include <cuda_fp16.h>
#include <math.h>
#include <stdint.h>

// Problem sizes
#define NB 2048
#define ND 64
#define NL 64
#define NH 512

// SMEM layout (in halves)
#define ZSTRIDE 72            // 64 + 8 pad -> conflict-free mma A loads
#define HSTRIDE 520           // 512 + 8 pad
#define BUF0_OFF (64 * ZSTRIDE)                 // after z tile
#define BUF1_OFF (BUF0_OFF + 64 * HSTRIDE)
#define SMEM_HALVES (BUF1_OFF + 64 * HSTRIDE)   // 71168 halves
#define SMEM_BYTES (SMEM_HALVES * 2 + 2 * 64 * 4 + 16)

// fp16 transposed weights: Wt[n][k] (k contiguous), [0]=s, [1]=t
__device__ __half g_Wt1[2][NH * NL];   // [512][64]
__device__ __half g_Wt2[2][NH * NH];   // [512][512]
__device__ __half g_Wt3[2][NH * NH];   // [512][512]
__device__ __half g_Wt4[2][ND * NH];   // [64][512]

__global__ void convert_kernel(const float* __restrict__ sW1, const float* __restrict__ sW2,
                               const float* __restrict__ sW3, const float* __restrict__ sW4,
                               const float* __restrict__ tW1, const float* __restrict__ tW2,
                               const float* __restrict__ tW3, const float* __restrict__ tW4) {
    int i = blockIdx.x * blockDim.x + threadIdx.x;
    const float* w1[2] = {sW1, tW1};
    const float* w2[2] = {sW2, tW2};
    const float* w3[2] = {sW3, tW3};
    const float* w4[2] = {sW4, tW4};
#pragma unroll
    for (int m = 0; m < 2; m++) {
        if (i < NL * NH) {              // W1: (64,512) row-major -> [n*64+k]
            int k = i >> 9, n = i & 511;
            g_Wt1[m][n * NL + k] = __float2half_rn(w1[m][i]);
        }
        if (i < NH * NH) {              // W2/W3: (512,512) -> [n*512+k]
            int k = i >> 9, n = i & 511;
            g_Wt2[m][n * NH + k] = __float2half_rn(w2[m][i]);
            g_Wt3[m][n * NH + k] = __float2half_rn(w3[m][i]);
        }
        if (i < NH * ND) {              // W4: (512,64) -> [n*512+k]
            int k = i >> 6, n = i & 63;
            g_Wt4[m][n * NH + k] = __float2half_rn(w4[m][i]);
        }
    }
}

__device__ __forceinline__ float tanh_approx(float x) {
    float y;
    asm("tanh.approx.f32 %0, %1;" : "=f"(y) : "f"(x));
    return y;
}

__device__ __forceinline__ void mma_m16n8k16(float c[4], const uint32_t a[4], const uint32_t b[2]) {
    asm volatile(
        "mma.sync.aligned.m16n8k16.row.col.f32.f16.f16.f32 "
        "{%0,%1,%2,%3}, {%4,%5,%6,%7}, {%8,%9}, {%0,%1,%2,%3};\n"
        : "+f"(c[0]), "+f"(c[1]), "+f"(c[2]), "+f"(c[3])
        : "r"(a[0]), "r"(a[1]), "r"(a[2]), "r"(a[3]), "r"(b[0]), "r"(b[1]));
}

// One dense layer: Out(64 x 512) = tanh(A(64 x K) @ W(K x 512) + bias)
// A in SMEM fp16 (row stride AS halves), W given transposed fp16 [n][k] in GMEM,
// Out written to SMEM fp16 (row stride HSTRIDE).
template <int K, int AS>
__device__ __forceinline__ void mlp_layer(const __half* __restrict__ A,
                                          const __half* __restrict__ Wt,
                                          const float* __restrict__ bias,
                                          __half* __restrict__ Out) {
    const int lane = threadIdx.x & 31;
    const int warp = threadIdx.x >> 5;
    const int g = lane >> 2;    // 0..7
    const int tg = lane & 3;    // 0..3

#pragma unroll
    for (int chunk = 0; chunk < 2; chunk++) {
        const int ncol0 = chunk * 256 + warp * 32;   // this warp's 32 columns

        float c[4][4][4];
#pragma unroll
        for (int rt = 0; rt < 4; rt++)
#pragma unroll
            for (int nt = 0; nt < 4; nt++)
#pragma unroll
                for (int r = 0; r < 4; r++) c[rt][nt][r] = 0.f;

        // B fragment base pointers: element (n = ncol0+nt*8+g, k = tg*2)
        const uint32_t* bp[4];
#pragma unroll
        for (int nt = 0; nt < 4; nt++)
            bp[nt] = reinterpret_cast<const uint32_t*>(Wt + (ncol0 + nt * 8 + g) * K + tg * 2);

        uint32_t bc[4][2], bn[4][2];
#pragma unroll
        for (int nt = 0; nt < 4; nt++) {
            bc[nt][0] = bp[nt][0];
            bc[nt][1] = bp[nt][4];     // k + 8
        }

#pragma unroll 2
        for (int k0 = 0; k0 < K; k0 += 16) {
            // prefetch next k-slice of B
            if (k0 + 16 < K) {
                const int o = (k0 + 16) >> 1;
#pragma unroll
                for (int nt = 0; nt < 4; nt++) {
                    bn[nt][0] = bp[nt][o];
                    bn[nt][1] = bp[nt][o + 4];
                }
            }
            // A fragments from SMEM (conflict-free: bank = 4g + tg)
            uint32_t a[4][4];
#pragma unroll
            for (int rt = 0; rt < 4; rt++) {
                const __half* ap = A + (rt * 16 + g) * AS + k0 + tg * 2;
                a[rt][0] = *reinterpret_cast<const uint32_t*>(ap);
                a[rt][1] = *reinterpret_cast<const uint32_t*>(ap + 8 * AS);
                a[rt][2] = *reinterpret_cast<const uint32_t*>(ap + 8);
                a[rt][3] = *reinterpret_cast<const uint32_t*>(ap + 8 * AS + 8);
            }
#pragma unroll
            for (int rt = 0; rt < 4; rt++)
#pragma unroll
                for (int nt = 0; nt < 4; nt++)
                    mma_m16n8k16(c[rt][nt], a[rt], bc[nt]);
#pragma unroll
            for (int nt = 0; nt < 4; nt++) {
                bc[nt][0] = bn[nt][0];
                bc[nt][1] = bn[nt][1];
            }
        }

        // epilogue: + bias, tanh, pack to half2, store to Out
#pragma unroll
        for (int nt = 0; nt < 4; nt++) {
            const int n0 = ncol0 + nt * 8 + tg * 2;
            const float2 bb = *reinterpret_cast<const float2*>(bias + n0);
#pragma unroll
            for (int rt = 0; rt < 4; rt++) {
                float v0 = tanh_approx(c[rt][nt][0] + bb.x);
                float v1 = tanh_approx(c[rt][nt][1] + bb.y);
                float v2 = tanh_approx(c[rt][nt][2] + bb.x);
                float v3 = tanh_approx(c[rt][nt][3] + bb.y);
                *reinterpret_cast<__half2*>(Out + (rt * 16 + g) * HSTRIDE + n0) =
                    __floats2half2_rn(v0, v1);
                *reinterpret_cast<__half2*>(Out + (rt * 16 + g + 8) * HSTRIDE + n0) =
                    __floats2half2_rn(v2, v3);
            }
        }
    }
}

// Diagonal of layer 4: for row r, out[r] = dot(h3[r,:], W4[:, r]) + b4[r]
__device__ __forceinline__ void diag_dot(const __half* __restrict__ h3,
                                         const __half* __restrict__ Wt4,
                                         const float* __restrict__ b4,
                                         float* __restrict__ dout) {
    const int t = threadIdx.x;
    const int r = t >> 2, q = t & 3;
    const __half2* hp = reinterpret_cast<const __half2*>(h3 + r * HSTRIDE);
    const __half2* wp = reinterpret_cast<const __half2*>(Wt4 + r * NH);
    float acc = 0.f;
#pragma unroll 8
    for (int j = q * 64; j < q * 64 + 64; j++) {
        float2 hv = __half22float2(hp[j]);
        float2 wv = __half22float2(wp[j]);
        acc = fmaf(hv.x, wv.x, acc);
        acc = fmaf(hv.y, wv.y, acc);
    }
    acc += __shfl_xor_sync(0xFFFFFFFFu, acc, 1);
    acc += __shfl_xor_sync(0xFFFFFFFFu, acc, 2);
    if (q == 0) dout[r] = acc + b4[r];
}

__device__ __forceinline__ void run_mlp(const __half* zs, __half* buf0, __half* buf1,
                                        const __half* Wt1, const __half* Wt2,
                                        const __half* Wt3, const __half* Wt4,
                                        const float* b1, const float* b2,
                                        const float* b3, const float* b4,
                                        float* dout) {
    mlp_layer<NL, ZSTRIDE>(zs, Wt1, b1, buf1);
    __syncthreads();
    mlp_layer<NH, HSTRIDE>(buf1, Wt2, b2, buf0);
    __syncthreads();
    mlp_layer<NH, HSTRIDE>(buf0, Wt3, b3, buf1);
    __syncthreads();
    diag_dot(buf1, Wt4, b4, dout);
    __syncthreads();
}

__global__ __launch_bounds__(256, 1)
void decoder_kernel(const float* __restrict__ x, const float* __restrict__ koop,
                    const float* __restrict__ sb1, const float* __restrict__ sb2,
                    const float* __restrict__ sb3, const float* __restrict__ sb4,
                    const float* __restrict__ tb1, const float* __restrict__ tb2,
                    const float* __restrict__ tb3, const float* __restrict__ tb4,
                    float* __restrict__ out) {
    extern __shared__ __half smem[];
    __half* zs = smem;                 // 64 x 72 (z = koopman[b]^T, fp16)
    __half* buf0 = smem + BUF0_OFF;    // 64 x 520
    __half* buf1 = smem + BUF1_OFF;    // 64 x 520
    float* ds = reinterpret_cast<float*>(smem + SMEM_HALVES);
    float* dt = ds + 64;

    const int b = blockIdx.x;
    const float* kb = koop + b * (NL * ND);

    // Load + transpose z: z[d][l] = koopman[b][l][d] (coalesced reads)
    for (int i = threadIdx.x; i < NL * ND; i += 256) {
        int l = i >> 6, d = i & 63;
        zs[d * ZSTRIDE + l] = __float2half_rn(kb[i]);
    }
    __syncthreads();

    run_mlp(zs, buf0, buf1, g_Wt1[0], g_Wt2[0], g_Wt3[0], g_Wt4[0],
            sb1, sb2, sb3, sb4, ds);
    run_mlp(zs, buf0, buf1, g_Wt1[1], g_Wt2[1], g_Wt3[1], g_Wt4[1],
            tb1, tb2, tb3, tb4, dt);
    __syncthreads();

    if (threadIdx.x < 64) {
        const int r = threadIdx.x;
        out[b * ND + r] = (x[b * ND + r] - dt[r]) * expf(-ds[r]);
    }
}

extern "C" void kernel_launch(void* const* d_in, const int* in_sizes, int n_in,
                              void* d_out, int out_size) {
    (void)in_sizes; (void)n_in; (void)out_size;
    const float* x   = (const float*)d_in[0];
    const float* kp  = (const float*)d_in[1];
    const float* sW1 = (const float*)d_in[2];
    const float* sb1 = (const float*)d_in[3];
    const float* sW2 = (const float*)d_in[4];
    const float* sb2 = (const float*)d_in[5];
    const float* sW3 = (const float*)d_in[6];
    const float* sb3 = (const float*)d_in[7];
    const float* sW4 = (const float*)d_in[8];
    const float* sb4 = (const float*)d_in[9];
    const float* tW1 = (const float*)d_in[10];
    const float* tb1 = (const float*)d_in[11];
    const float* tW2 = (const float*)d_in[12];
    const float* tb2 = (const float*)d_in[13];
    const float* tW3 = (const float*)d_in[14];
    const float* tb3 = (const float*)d_in[15];
    const float* tW4 = (const float*)d_in[16];
    const float* tb4 = (const float*)d_in[17];
    float* out = (float*)d_out;

    convert_kernel<<<(NH * NH + 255) / 256, 256>>>(sW1, sW2, sW3, sW4, tW1, tW2, tW3, tW4);

    cudaFuncSetAttribute(decoder_kernel, cudaFuncAttributeMaxDynamicSharedMemorySize, SMEM_BYTES);
    decoder_kernel<<<NB, 256, SMEM_BYTES>>>(x, kp,
                                            sb1, sb2, sb3, sb4,
                                            tb1, tb2, tb3, tb4,
                                            out);
}

// round 3
// speedup vs baseline: 1.6421x; 1.6421x over previous
#include <cuda_runtime.h>
#include <cuda_fp16.h>
#include <math.h>
#include <stdint.h>

// Problem sizes
#define NB 2048
#define ND 64
#define NL 64
#define NH 512

// SMEM layout (in halves)
#define ZSTRIDE 72            // 64 + 8 pad -> conflict-free ldmatrix (144B row stride)
#define HSTRIDE 520           // 512 + 8 pad (1040B row stride)
#define BUF0_OFF (64 * ZSTRIDE)
#define BUF1_OFF (BUF0_OFF + 64 * HSTRIDE)
#define SMEM_HALVES (BUF1_OFF + 64 * HSTRIDE)
#define SMEM_BYTES (SMEM_HALVES * 2 + 2 * 64 * 4 + 16)

// Fragment-major fp16 weights for mma.m16n8k16 B operand.
// Index: ((n8 * Ksteps + kstep) * 32 + lane) * 2 + w
//   n = n8*8 + (lane>>2), k = kstep*16 + (lane&3)*2 + w*8, value = half2(W[k][n], W[k+1][n])
__device__ __half2 g_Wf1[2][NL * NH / 2];   // Ksteps = 4
__device__ __half2 g_Wf2[2][NH * NH / 2];   // Ksteps = 32
__device__ __half2 g_Wf3[2][NH * NH / 2];   // Ksteps = 32
__device__ __half  g_Wt4[2][ND * NH];       // [n][k] for diagonal dot

__global__ void convert_kernel(const float* __restrict__ sW1, const float* __restrict__ sW2,
                               const float* __restrict__ sW3, const float* __restrict__ sW4,
                               const float* __restrict__ tW1, const float* __restrict__ tW2,
                               const float* __restrict__ tW3, const float* __restrict__ tW4) {
    const int i = blockIdx.x * blockDim.x + threadIdx.x;
    const float* w1[2] = {sW1, tW1};
    const float* w2[2] = {sW2, tW2};
    const float* w3[2] = {sW3, tW3};
    const float* w4[2] = {sW4, tW4};
#pragma unroll
    for (int m = 0; m < 2; m++) {
        if (i < NH * NH / 2) {   // W2 / W3, K = 512, Ksteps = 32
            const int w = i & 1, lane = (i >> 1) & 31, kstep = (i >> 6) & 31, n8 = i >> 11;
            const int n = n8 * 8 + (lane >> 2);
            const int k = kstep * 16 + (lane & 3) * 2 + w * 8;
            g_Wf2[m][i] = __floats2half2_rn(w2[m][k * NH + n], w2[m][(k + 1) * NH + n]);
            g_Wf3[m][i] = __floats2half2_rn(w3[m][k * NH + n], w3[m][(k + 1) * NH + n]);
        }
        if (i < NL * NH / 2) {   // W1, K = 64, Ksteps = 4
            const int w = i & 1, lane = (i >> 1) & 31, kstep = (i >> 6) & 3, n8 = i >> 8;
            const int n = n8 * 8 + (lane >> 2);
            const int k = kstep * 16 + (lane & 3) * 2 + w * 8;
            g_Wf1[m][i] = __floats2half2_rn(w1[m][k * NH + n], w1[m][(k + 1) * NH + n]);
        }
        if (i < NH * ND) {       // W4 (512,64) row-major -> [n][k]
            const int k = i >> 6, n = i & 63;
            g_Wt4[m][n * NH + k] = __float2half_rn(w4[m][i]);
        }
    }
}

__device__ __forceinline__ float tanh_approx(float x) {
    float y;
    asm("tanh.approx.f32 %0, %1;" : "=f"(y) : "f"(x));
    return y;
}

__device__ __forceinline__ void mma_m16n8k16(float c[4], const uint32_t a[4], const uint2 b) {
    asm volatile(
        "mma.sync.aligned.m16n8k16.row.col.f32.f16.f16.f32 "
        "{%0,%1,%2,%3}, {%4,%5,%6,%7}, {%8,%9}, {%0,%1,%2,%3};\n"
        : "+f"(c[0]), "+f"(c[1]), "+f"(c[2]), "+f"(c[3])
        : "r"(a[0]), "r"(a[1]), "r"(a[2]), "r"(a[3]), "r"(b.x), "r"(b.y));
}

__device__ __forceinline__ void ldsm4(uint32_t a[4], uint32_t addr) {
    asm volatile("ldmatrix.sync.aligned.m8n8.x4.shared.b16 {%0,%1,%2,%3}, [%4];"
                 : "=r"(a[0]), "=r"(a[1]), "=r"(a[2]), "=r"(a[3]) : "r"(addr));
}

// One dense layer: Out(64 x 512) = tanh(A(64 x K) @ W(K x 512) + bias)
// A: SMEM fp16 (row stride AS halves); Wf: fragment-major fp16 in GMEM; Out: SMEM fp16.
template <int K, int AS>
__device__ __noinline__ void mlp_layer(const __half* __restrict__ A,
                                       const __half2* __restrict__ Wf,
                                       const float* __restrict__ bias,
                                       __half* __restrict__ Out) {
    constexpr int Ks = K / 16;
    const int lane = threadIdx.x & 31;
    const int warp = threadIdx.x >> 5;
    const int g = lane >> 2;
    const int tg = lane & 3;

    // Per-lane ldmatrix base addresses for the 4 row-tiles (rt)
    uint32_t abase[4];
    {
        const __half* ap = A + (lane & 15) * AS + ((lane >> 4) << 3);
#pragma unroll
        for (int rt = 0; rt < 4; rt++)
            abase[rt] = (uint32_t)__cvta_generic_to_shared(ap + rt * 16 * AS);
    }

#pragma unroll
    for (int chunk = 0; chunk < 2; chunk++) {
        const int ncol0 = chunk * 256 + warp * 32;
        const int n8_0 = ncol0 >> 3;

        const uint2* bp[4];
#pragma unroll
        for (int nt = 0; nt < 4; nt++)
            bp[nt] = reinterpret_cast<const uint2*>(Wf) + (n8_0 + nt) * (Ks * 32) + lane;

        float c[4][4][4];
#pragma unroll
        for (int rt = 0; rt < 4; rt++)
#pragma unroll
            for (int nt = 0; nt < 4; nt++)
#pragma unroll
                for (int r = 0; r < 4; r++) c[rt][nt][r] = 0.f;

        uint2 b[4][4];       // ring buffer over ksteps (distance-2 prefetch)
        uint32_t a[2][4][4]; // double buffer (distance-1 prefetch)

#pragma unroll
        for (int j = 0; j < 2 && j < Ks; j++)
#pragma unroll
            for (int nt = 0; nt < 4; nt++) b[j][nt] = bp[nt][j * 32];
#pragma unroll
        for (int rt = 0; rt < 4; rt++) ldsm4(a[0][rt], abase[rt]);

#pragma unroll 4
        for (int ks = 0; ks < Ks; ks++) {
            const int cur = ks & 1;
            const int kb = (ks + 2 < Ks) ? (ks + 2) : (Ks - 1);
#pragma unroll
            for (int nt = 0; nt < 4; nt++) b[(ks + 2) & 3][nt] = bp[nt][kb * 32];
            const int ka = (ks + 1 < Ks) ? (ks + 1) : (Ks - 1);
#pragma unroll
            for (int rt = 0; rt < 4; rt++) ldsm4(a[cur ^ 1][rt], abase[rt] + ka * 32);
#pragma unroll
            for (int rt = 0; rt < 4; rt++)
#pragma unroll
                for (int nt = 0; nt < 4; nt++)
                    mma_m16n8k16(c[rt][nt], a[cur][rt], b[ks & 3][nt]);
        }

        // epilogue: + bias, tanh, pack to half2, store
#pragma unroll
        for (int nt = 0; nt < 4; nt++) {
            const int n0 = ncol0 + nt * 8 + tg * 2;
            const float2 bb = *reinterpret_cast<const float2*>(bias + n0);
#pragma unroll
            for (int rt = 0; rt < 4; rt++) {
                float v0 = tanh_approx(c[rt][nt][0] + bb.x);
                float v1 = tanh_approx(c[rt][nt][1] + bb.y);
                float v2 = tanh_approx(c[rt][nt][2] + bb.x);
                float v3 = tanh_approx(c[rt][nt][3] + bb.y);
                *reinterpret_cast<__half2*>(Out + (rt * 16 + g) * HSTRIDE + n0) =
                    __floats2half2_rn(v0, v1);
                *reinterpret_cast<__half2*>(Out + (rt * 16 + g + 8) * HSTRIDE + n0) =
                    __floats2half2_rn(v2, v3);
            }
        }
    }
}

// Diagonal of layer 4: out[r] = dot(h3[r,:], W4[:, r]) + b4[r]
__device__ __forceinline__ void diag_dot(const __half* __restrict__ h3,
                                         const __half* __restrict__ Wt4,
                                         const float* __restrict__ b4,
                                         float* __restrict__ dout) {
    const int t = threadIdx.x;
    const int r = t >> 2, q = t & 3;
    const __half2* hp = reinterpret_cast<const __half2*>(h3 + r * HSTRIDE);
    const __half2* wp = reinterpret_cast<const __half2*>(Wt4 + r * NH);
    float acc = 0.f;
#pragma unroll 8
    for (int j = q * 64; j < q * 64 + 64; j++) {
        float2 hv = __half22float2(hp[j]);
        float2 wv = __half22float2(wp[j]);
        acc = fmaf(hv.x, wv.x, acc);
        acc = fmaf(hv.y, wv.y, acc);
    }
    acc += __shfl_xor_sync(0xFFFFFFFFu, acc, 1);
    acc += __shfl_xor_sync(0xFFFFFFFFu, acc, 2);
    if (q == 0) dout[r] = acc + b4[r];
}

__device__ __forceinline__ void run_mlp(const __half* zs, __half* buf0, __half* buf1,
                                        const __half2* Wf1, const __half2* Wf2,
                                        const __half2* Wf3, const __half* Wt4,
                                        const float* b1, const float* b2,
                                        const float* b3, const float* b4,
                                        float* dout) {
    mlp_layer<NL, ZSTRIDE>(zs, Wf1, b1, buf1);
    __syncthreads();
    mlp_layer<NH, HSTRIDE>(buf1, Wf2, b2, buf0);
    __syncthreads();
    mlp_layer<NH, HSTRIDE>(buf0, Wf3, b3, buf1);
    __syncthreads();
    diag_dot(buf1, Wt4, b4, dout);
    __syncthreads();
}

__global__ __launch_bounds__(256, 1)
void decoder_kernel(const float* __restrict__ x, const float* __restrict__ koop,
                    const float* __restrict__ sb1, const float* __restrict__ sb2,
                    const float* __restrict__ sb3, const float* __restrict__ sb4,
                    const float* __restrict__ tb1, const float* __restrict__ tb2,
                    const float* __restrict__ tb3, const float* __restrict__ tb4,
                    float* __restrict__ out) {
    extern __shared__ __half smem[];
    __half* zs = smem;                 // 64 x 72
    __half* buf0 = smem + BUF0_OFF;    // 64 x 520
    __half* buf1 = smem + BUF1_OFF;    // 64 x 520
    float* ds = reinterpret_cast<float*>(smem + SMEM_HALVES);
    float* dt = ds + 64;

    const int b = blockIdx.x;
    const float* kb = koop + b * (NL * ND);

    // Load + transpose z: z[d][l] = koopman[b][l][d]
    for (int i = threadIdx.x; i < NL * ND; i += 256) {
        int l = i >> 6, d = i & 63;
        zs[d * ZSTRIDE + l] = __float2half_rn(kb[i]);
    }
    __syncthreads();

    run_mlp(zs, buf0, buf1, g_Wf1[0], g_Wf2[0], g_Wf3[0], g_Wt4[0],
            sb1, sb2, sb3, sb4, ds);
    run_mlp(zs, buf0, buf1, g_Wf1[1], g_Wf2[1], g_Wf3[1], g_Wt4[1],
            tb1, tb2, tb3, tb4, dt);
    __syncthreads();

    if (threadIdx.x < 64) {
        const int r = threadIdx.x;
        out[b * ND + r] = (x[b * ND + r] - dt[r]) * expf(-ds[r]);
    }
}

extern "C" void kernel_launch(void* const* d_in, const int* in_sizes, int n_in,
                              void* d_out, int out_size) {
    (void)in_sizes; (void)n_in; (void)out_size;
    const float* x   = (const float*)d_in[0];
    const float* kp  = (const float*)d_in[1];
    const float* sW1 = (const float*)d_in[2];
    const float* sb1 = (const float*)d_in[3];
    const float* sW2 = (const float*)d_in[4];
    const float* sb2 = (const float*)d_in[5];
    const float* sW3 = (const float*)d_in[6];
    const float* sb3 = (const float*)d_in[7];
    const float* sW4 = (const float*)d_in[8];
    const float* sb4 = (const float*)d_in[9];
    const float* tW1 = (const float*)d_in[10];
    const float* tb1 = (const float*)d_in[11];
    const float* tW2 = (const float*)d_in[12];
    const float* tb2 = (const float*)d_in[13];
    const float* tW3 = (const float*)d_in[14];
    const float* tb3 = (const float*)d_in[15];
    const float* tW4 = (const float*)d_in[16];
    const float* tb4 = (const float*)d_in[17];
    float* out = (float*)d_out;

    convert_kernel<<<(NH * NH / 2 + 255) / 256, 256>>>(sW1, sW2, sW3, sW4, tW1, tW2, tW3, tW4);

    cudaFuncSetAttribute(decoder_kernel, cudaFuncAttributeMaxDynamicSharedMemorySize, SMEM_BYTES);
    decoder_kernel<<<NB, 256, SMEM_BYTES>>>(x, kp,
                                            sb1, sb2, sb3, sb4,
                                            tb1, tb2, tb3, tb4,
                                            out);
}

// round 4
// speedup vs baseline: 1.7117x; 1.0424x over previous
#include <cuda_runtime.h>
#include <cuda_fp16.h>
#include <math.h>
#include <stdint.h>

// Problem sizes
#define NB 2048
#define ND 64
#define NL 64
#define NH 512

// SMEM layout (in halves)
#define ZSTRIDE 72            // 64 + 8 pad -> conflict-free ldmatrix (144B row stride)
#define HSTRIDE 520           // 512 + 8 pad (1040B row stride)
#define BUF0_OFF (64 * ZSTRIDE)
#define BUF1_OFF (BUF0_OFF + 64 * HSTRIDE)
#define SMEM_HALVES (BUF1_OFF + 64 * HSTRIDE)
#define SMEM_BYTES (SMEM_HALVES * 2 + 2 * 64 * 4 + 16)

// Fragment-major fp16 weights, PAIR-PACKED for LDG.128:
// uint4 index ((n8 * Ks/2 + ks2) * 32 + lane); .xy = kstep 2*ks2 frag (w0,w1),
// .zw = kstep 2*ks2+1 frag. Within a frag: n = n8*8 + (lane>>2),
// k = kstep*16 + (lane&3)*2 + w*8, half2 = (W[k][n], W[k+1][n]).
__device__ __half2 g_Wf1[2][NL * NH / 2];   // Ks = 4
__device__ __half2 g_Wf2[2][NH * NH / 2];   // Ks = 32
__device__ __half2 g_Wf3[2][NH * NH / 2];   // Ks = 32
__device__ __half  g_Wt4[2][ND * NH];       // [n][k] for diagonal dot

__global__ void convert_kernel(const float* __restrict__ sW1, const float* __restrict__ sW2,
                               const float* __restrict__ sW3, const float* __restrict__ sW4,
                               const float* __restrict__ tW1, const float* __restrict__ tW2,
                               const float* __restrict__ tW3, const float* __restrict__ tW4) {
    const int i = blockIdx.x * blockDim.x + threadIdx.x;
    const float* w1[2] = {sW1, tW1};
    const float* w2[2] = {sW2, tW2};
    const float* w3[2] = {sW3, tW3};
    const float* w4[2] = {sW4, tW4};
#pragma unroll
    for (int m = 0; m < 2; m++) {
        if (i < NH * NH / 2) {   // W2/W3: Ks = 32, Ks2 = 16
            const int c = i & 3, w = c & 1, sub = c >> 1;
            const int lane = (i >> 2) & 31, ks2 = (i >> 7) & 15, n8 = i >> 11;
            const int kstep = ks2 * 2 + sub;
            const int n = n8 * 8 + (lane >> 2);
            const int k = kstep * 16 + (lane & 3) * 2 + w * 8;
            g_Wf2[m][i] = __floats2half2_rn(w2[m][k * NH + n], w2[m][(k + 1) * NH + n]);
            g_Wf3[m][i] = __floats2half2_rn(w3[m][k * NH + n], w3[m][(k + 1) * NH + n]);
        }
        if (i < NL * NH / 2) {   // W1: Ks = 4, Ks2 = 2
            const int c = i & 3, w = c & 1, sub = c >> 1;
            const int lane = (i >> 2) & 31, ks2 = (i >> 7) & 1, n8 = i >> 8;
            const int kstep = ks2 * 2 + sub;
            const int n = n8 * 8 + (lane >> 2);
            const int k = kstep * 16 + (lane & 3) * 2 + w * 8;
            g_Wf1[m][i] = __floats2half2_rn(w1[m][k * NH + n], w1[m][(k + 1) * NH + n]);
        }
        if (i < NH * ND) {       // W4 (512,64) row-major -> [n][k]
            const int k = i >> 6, n = i & 63;
            g_Wt4[m][n * NH + k] = __float2half_rn(w4[m][i]);
        }
    }
}

__device__ __forceinline__ float tanh_approx(float x) {
    float y;
    asm("tanh.approx.f32 %0, %1;" : "=f"(y) : "f"(x));
    return y;
}

__device__ __forceinline__ void mma_m16n8k16(float c[4], const uint32_t a[4],
                                             uint32_t b0, uint32_t b1) {
    asm volatile(
        "mma.sync.aligned.m16n8k16.row.col.f32.f16.f16.f32 "
        "{%0,%1,%2,%3}, {%4,%5,%6,%7}, {%8,%9}, {%0,%1,%2,%3};\n"
        : "+f"(c[0]), "+f"(c[1]), "+f"(c[2]), "+f"(c[3])
        : "r"(a[0]), "r"(a[1]), "r"(a[2]), "r"(a[3]), "r"(b0), "r"(b1));
}

__device__ __forceinline__ void ldsm4(uint32_t a[4], uint32_t addr) {
    asm volatile("ldmatrix.sync.aligned.m8n8.x4.shared.b16 {%0,%1,%2,%3}, [%4];"
                 : "=r"(a[0]), "=r"(a[1]), "=r"(a[2]), "=r"(a[3]) : "r"(addr));
}

// One dense layer: Out(64 x 512) = tanh(A(64 x K) @ W(K x 512) + bias)
// 16 warps; warp w owns output columns [w*32, w*32+32).
template <int K, int AS>
__device__ __noinline__ void mlp_layer(const __half* __restrict__ A,
                                       const __half2* __restrict__ Wf,
                                       const float* __restrict__ bias,
                                       __half* __restrict__ Out) {
    constexpr int Ks = K / 16;
    constexpr int Ks2 = Ks / 2;
    const int lane = threadIdx.x & 31;
    const int warp = threadIdx.x >> 5;
    const int g = lane >> 2;
    const int tg = lane & 3;
    const int ncol0 = warp * 32;

    // ldmatrix base addresses for the 4 row tiles
    uint32_t abase[4];
    {
        const __half* ap = A + (lane & 15) * AS + ((lane >> 4) << 3);
#pragma unroll
        for (int rt = 0; rt < 4; rt++)
            abase[rt] = (uint32_t)__cvta_generic_to_shared(ap + rt * 16 * AS);
    }

    // B: single base pointer; nt offsets are compile-time immediates
    const uint4* bq = reinterpret_cast<const uint4*>(Wf) + (warp * 4) * (Ks2 * 32) + lane;

    float c[4][4][4];
#pragma unroll
    for (int rt = 0; rt < 4; rt++)
#pragma unroll
        for (int nt = 0; nt < 4; nt++)
#pragma unroll
            for (int r = 0; r < 4; r++) c[rt][nt][r] = 0.f;

    uint4 bc[4], bn[4];
#pragma unroll
    for (int nt = 0; nt < 4; nt++) bc[nt] = bq[nt * (Ks2 * 32)];

#pragma unroll 2
    for (int ks2 = 0; ks2 < Ks2; ks2++) {
        const int kn = (ks2 + 1 < Ks2) ? (ks2 + 1) : (Ks2 - 1);
#pragma unroll
        for (int nt = 0; nt < 4; nt++) bn[nt] = bq[nt * (Ks2 * 32) + kn * 32];

        uint32_t a[4][4];
#pragma unroll
        for (int rt = 0; rt < 4; rt++) ldsm4(a[rt], abase[rt] + (ks2 * 2) * 32);
#pragma unroll
        for (int rt = 0; rt < 4; rt++)
#pragma unroll
            for (int nt = 0; nt < 4; nt++)
                mma_m16n8k16(c[rt][nt], a[rt], bc[nt].x, bc[nt].y);

#pragma unroll
        for (int rt = 0; rt < 4; rt++) ldsm4(a[rt], abase[rt] + (ks2 * 2 + 1) * 32);
#pragma unroll
        for (int rt = 0; rt < 4; rt++)
#pragma unroll
            for (int nt = 0; nt < 4; nt++)
                mma_m16n8k16(c[rt][nt], a[rt], bc[nt].z, bc[nt].w);

#pragma unroll
        for (int nt = 0; nt < 4; nt++) bc[nt] = bn[nt];
    }

    // epilogue: + bias, tanh, pack to half2, store
#pragma unroll
    for (int nt = 0; nt < 4; nt++) {
        const int n0 = ncol0 + nt * 8 + tg * 2;
        const float2 bb = *reinterpret_cast<const float2*>(bias + n0);
#pragma unroll
        for (int rt = 0; rt < 4; rt++) {
            float v0 = tanh_approx(c[rt][nt][0] + bb.x);
            float v1 = tanh_approx(c[rt][nt][1] + bb.y);
            float v2 = tanh_approx(c[rt][nt][2] + bb.x);
            float v3 = tanh_approx(c[rt][nt][3] + bb.y);
            *reinterpret_cast<__half2*>(Out + (rt * 16 + g) * HSTRIDE + n0) =
                __floats2half2_rn(v0, v1);
            *reinterpret_cast<__half2*>(Out + (rt * 16 + g + 8) * HSTRIDE + n0) =
                __floats2half2_rn(v2, v3);
        }
    }
}

// Diagonal of layer 4: out[r] = dot(h3[r,:], W4[:, r]) + b4[r]  (512 threads)
__device__ __forceinline__ void diag_dot(const __half* __restrict__ h3,
                                         const __half* __restrict__ Wt4,
                                         const float* __restrict__ b4,
                                         float* __restrict__ dout) {
    const int t = threadIdx.x;
    const int r = t >> 3, q = t & 7;     // 8 threads per row
    const __half2* hp = reinterpret_cast<const __half2*>(h3 + r * HSTRIDE);
    const __half2* wp = reinterpret_cast<const __half2*>(Wt4 + r * NH);
    float acc = 0.f;
#pragma unroll 8
    for (int j = q * 32; j < q * 32 + 32; j++) {
        float2 hv = __half22float2(hp[j]);
        float2 wv = __half22float2(wp[j]);
        acc = fmaf(hv.x, wv.x, acc);
        acc = fmaf(hv.y, wv.y, acc);
    }
    acc += __shfl_xor_sync(0xFFFFFFFFu, acc, 1);
    acc += __shfl_xor_sync(0xFFFFFFFFu, acc, 2);
    acc += __shfl_xor_sync(0xFFFFFFFFu, acc, 4);
    if (q == 0) dout[r] = acc + b4[r];
}

__device__ __forceinline__ void run_mlp(const __half* zs, __half* buf0, __half* buf1,
                                        const __half2* Wf1, const __half2* Wf2,
                                        const __half2* Wf3, const __half* Wt4,
                                        const float* b1, const float* b2,
                                        const float* b3, const float* b4,
                                        float* dout) {
    mlp_layer<NL, ZSTRIDE>(zs, Wf1, b1, buf1);
    __syncthreads();
    mlp_layer<NH, HSTRIDE>(buf1, Wf2, b2, buf0);
    __syncthreads();
    mlp_layer<NH, HSTRIDE>(buf0, Wf3, b3, buf1);
    __syncthreads();
    diag_dot(buf1, Wt4, b4, dout);
    __syncthreads();
}

__global__ __launch_bounds__(512, 1)
void decoder_kernel(const float* __restrict__ x, const float* __restrict__ koop,
                    const float* __restrict__ sb1, const float* __restrict__ sb2,
                    const float* __restrict__ sb3, const float* __restrict__ sb4,
                    const float* __restrict__ tb1, const float* __restrict__ tb2,
                    const float* __restrict__ tb3, const float* __restrict__ tb4,
                    float* __restrict__ out) {
    extern __shared__ __half smem[];
    __half* zs = smem;                 // 64 x 72
    __half* buf0 = smem + BUF0_OFF;    // 64 x 520
    __half* buf1 = smem + BUF1_OFF;    // 64 x 520
    float* ds = reinterpret_cast<float*>(smem + SMEM_HALVES);
    float* dt = ds + 64;

    const int b = blockIdx.x;
    const float* kb = koop + b * (NL * ND);

    // Load + transpose z: z[d][l] = koopman[b][l][d]
    for (int i = threadIdx.x; i < NL * ND; i += 512) {
        int l = i >> 6, d = i & 63;
        zs[d * ZSTRIDE + l] = __float2half_rn(kb[i]);
    }
    __syncthreads();

    run_mlp(zs, buf0, buf1, g_Wf1[0], g_Wf2[0], g_Wf3[0], g_Wt4[0],
            sb1, sb2, sb3, sb4, ds);
    run_mlp(zs, buf0, buf1, g_Wf1[1], g_Wf2[1], g_Wf3[1], g_Wt4[1],
            tb1, tb2, tb3, tb4, dt);
    __syncthreads();

    if (threadIdx.x < 64) {
        const int r = threadIdx.x;
        out[b * ND + r] = (x[b * ND + r] - dt[r]) * expf(-ds[r]);
    }
}

extern "C" void kernel_launch(void* const* d_in, const int* in_sizes, int n_in,
                              void* d_out, int out_size) {
    (void)in_sizes; (void)n_in; (void)out_size;
    const float* x   = (const float*)d_in[0];
    const float* kp  = (const float*)d_in[1];
    const float* sW1 = (const float*)d_in[2];
    const float* sb1 = (const float*)d_in[3];
    const float* sW2 = (const float*)d_in[4];
    const float* sb2 = (const float*)d_in[5];
    const float* sW3 = (const float*)d_in[6];
    const float* sb3 = (const float*)d_in[7];
    const float* sW4 = (const float*)d_in[8];
    const float* sb4 = (const float*)d_in[9];
    const float* tW1 = (const float*)d_in[10];
    const float* tb1 = (const float*)d_in[11];
    const float* tW2 = (const float*)d_in[12];
    const float* tb2 = (const float*)d_in[13];
    const float* tW3 = (const float*)d_in[14];
    const float* tb3 = (const float*)d_in[15];
    const float* tW4 = (const float*)d_in[16];
    const float* tb4 = (const float*)d_in[17];
    float* out = (float*)d_out;

    convert_kernel<<<(NH * NH / 2 + 255) / 256, 256>>>(sW1, sW2, sW3, sW4, tW1, tW2, tW3, tW4);

    cudaFuncSetAttribute(decoder_kernel, cudaFuncAttributeMaxDynamicSharedMemorySize, SMEM_BYTES);
    decoder_kernel<<<NB, 512, SMEM_BYTES>>>(x, kp,
                                            sb1, sb2, sb3, sb4,
                                            tb1, tb2, tb3, tb4,
                                            out);
}

// round 8
// speedup vs baseline: 1.7136x; 1.0011x over previous
#include <cuda_runtime.h>
#include <cuda_fp16.h>
#include <math.h>
#include <stdint.h>

// Problem sizes
#define NB 2048
#define ND 64
#define NL 64
#define NH 512

// SMEM layout (in halves)
#define ZSTRIDE 72            // 64 + 8 pad -> conflict-free ldmatrix (144B row stride)
#define HSTRIDE 520           // 512 + 8 pad (1040B row stride)
#define BUF0_OFF (64 * ZSTRIDE)
#define BUF1_OFF (BUF0_OFF + 64 * HSTRIDE)
#define SMEM_HALVES (BUF1_OFF + 64 * HSTRIDE)
#define SMEM_BYTES (SMEM_HALVES * 2 + 2 * 64 * 4 + 16)

// Fragment-major fp16 weights, PAIR-PACKED for LDG.128:
// uint4 index ((n8 * Ks/2 + ks2) * 32 + lane); .xy = kstep 2*ks2 frag (w0,w1),
// .zw = kstep 2*ks2+1 frag. Within a frag: n = n8*8 + (lane>>2),
// k = kstep*16 + (lane&3)*2 + w*8, half2 = (W[k][n], W[k+1][n]).
__device__ __half2 g_Wf1[2][NL * NH / 2];   // Ks = 4
__device__ __half2 g_Wf2[2][NH * NH / 2];   // Ks = 32
__device__ __half2 g_Wf3[2][NH * NH / 2];   // Ks = 32
__device__ __half  g_Wt4[2][ND * NH];       // [n][k] for diagonal dot

__global__ void convert_kernel(const float* __restrict__ sW1, const float* __restrict__ sW2,
                               const float* __restrict__ sW3, const float* __restrict__ sW4,
                               const float* __restrict__ tW1, const float* __restrict__ tW2,
                               const float* __restrict__ tW3, const float* __restrict__ tW4) {
    const int i = blockIdx.x * blockDim.x + threadIdx.x;
    const float* w1[2] = {sW1, tW1};
    const float* w2[2] = {sW2, tW2};
    const float* w3[2] = {sW3, tW3};
    const float* w4[2] = {sW4, tW4};
#pragma unroll
    for (int m = 0; m < 2; m++) {
        if (i < NH * NH / 2) {   // W2/W3: Ks = 32, Ks2 = 16
            const int c = i & 3, w = c & 1, sub = c >> 1;
            const int lane = (i >> 2) & 31, ks2 = (i >> 7) & 15, n8 = i >> 11;
            const int kstep = ks2 * 2 + sub;
            const int n = n8 * 8 + (lane >> 2);
            const int k = kstep * 16 + (lane & 3) * 2 + w * 8;
            g_Wf2[m][i] = __floats2half2_rn(w2[m][k * NH + n], w2[m][(k + 1) * NH + n]);
            g_Wf3[m][i] = __floats2half2_rn(w3[m][k * NH + n], w3[m][(k + 1) * NH + n]);
        }
        if (i < NL * NH / 2) {   // W1: Ks = 4, Ks2 = 2
            const int c = i & 3, w = c & 1, sub = c >> 1;
            const int lane = (i >> 2) & 31, ks2 = (i >> 7) & 1, n8 = i >> 8;
            const int kstep = ks2 * 2 + sub;
            const int n = n8 * 8 + (lane >> 2);
            const int k = kstep * 16 + (lane & 3) * 2 + w * 8;
            g_Wf1[m][i] = __floats2half2_rn(w1[m][k * NH + n], w1[m][(k + 1) * NH + n]);
        }
        if (i < NH * ND) {       // W4 (512,64) row-major -> [n][k]
            const int k = i >> 6, n = i & 63;
            g_Wt4[m][n * NH + k] = __float2half_rn(w4[m][i]);
        }
    }
}

__device__ __forceinline__ float tanh_approx(float x) {
    float y;
    asm("tanh.approx.f32 %0, %1;" : "=f"(y) : "f"(x));
    return y;
}

__device__ __forceinline__ void mma_m16n8k16(float c[4], const uint32_t a[4],
                                             uint32_t b0, uint32_t b1) {
    asm volatile(
        "mma.sync.aligned.m16n8k16.row.col.f32.f16.f16.f32 "
        "{%0,%1,%2,%3}, {%4,%5,%6,%7}, {%8,%9}, {%0,%1,%2,%3};\n"
        : "+f"(c[0]), "+f"(c[1]), "+f"(c[2]), "+f"(c[3])
        : "r"(a[0]), "r"(a[1]), "r"(a[2]), "r"(a[3]), "r"(b0), "r"(b1));
}

__device__ __forceinline__ void ldsm4(uint32_t a[4], uint32_t addr) {
    asm volatile("ldmatrix.sync.aligned.m8n8.x4.shared.b16 {%0,%1,%2,%3}, [%4];"
                 : "=r"(a[0]), "=r"(a[1]), "=r"(a[2]), "=r"(a[3]) : "r"(addr));
}

// One dense layer: Out(64 x 512) = tanh(A(64 x K) @ W(K x 512) + bias)
// 16 warps; warp w owns output columns [w*32, w*32+32).
// A-operand: rt-granular 2-deep ring (prefetch next rt frag before current mma group).
// B-operand: distance-1 uint4 double buffer (pair-packed LDG.128).
template <int K, int AS>
__device__ __noinline__ void mlp_layer(const __half* __restrict__ A,
                                       const __half2* __restrict__ Wf,
                                       const float* __restrict__ bias,
                                       __half* __restrict__ Out) {
    constexpr int Ks = K / 16;
    constexpr int Ks2 = Ks / 2;
    const int lane = threadIdx.x & 31;
    const int warp = threadIdx.x >> 5;
    const int g = lane >> 2;
    const int tg = lane & 3;
    const int ncol0 = warp * 32;

    // ldmatrix base addresses for the 4 row tiles
    uint32_t abase[4];
    {
        const __half* ap = A + (lane & 15) * AS + ((lane >> 4) << 3);
#pragma unroll
        for (int rt = 0; rt < 4; rt++)
            abase[rt] = (uint32_t)__cvta_generic_to_shared(ap + rt * 16 * AS);
    }

    // B: single base pointer; nt offsets are compile-time immediates
    const uint4* bq = reinterpret_cast<const uint4*>(Wf) + (warp * 4) * (Ks2 * 32) + lane;

    float c[4][4][4];
#pragma unroll
    for (int rt = 0; rt < 4; rt++)
#pragma unroll
        for (int nt = 0; nt < 4; nt++)
#pragma unroll
            for (int r = 0; r < 4; r++) c[rt][nt][r] = 0.f;

    uint4 bc[4], bn[4];
#pragma unroll
    for (int nt = 0; nt < 4; nt++) bc[nt] = bq[nt * (Ks2 * 32)];

    // A ring: 2 fragments deep, rotated at rt granularity
    uint32_t a[2][4];
    ldsm4(a[0], abase[0]);   // (rt=0, kstep=0)

#pragma unroll 4
    for (int ks2 = 0; ks2 < Ks2; ks2++) {
        const int kn = (ks2 + 1 < Ks2) ? (ks2 + 1) : (Ks2 - 1);
#pragma unroll
        for (int nt = 0; nt < 4; nt++) bn[nt] = bq[nt * (Ks2 * 32) + kn * 32];

#pragma unroll
        for (int sub = 0; sub < 2; sub++) {
            const int kk = ks2 * 2 + sub;
#pragma unroll
            for (int rt = 0; rt < 4; rt++) {
                // prefetch next rt fragment (wraps into next kstep at rt==3)
                const int nrt = (rt + 1) & 3;
                int nkk = (rt == 3) ? kk + 1 : kk;
                if (nkk > Ks - 1) nkk = Ks - 1;   // clamp (harmless reload at tail)
                ldsm4(a[(rt + 1) & 1], abase[nrt] + nkk * 32);
                if (sub == 0) {
#pragma unroll
                    for (int nt = 0; nt < 4; nt++)
                        mma_m16n8k16(c[rt][nt], a[rt & 1], bc[nt].x, bc[nt].y);
                } else {
#pragma unroll
                    for (int nt = 0; nt < 4; nt++)
                        mma_m16n8k16(c[rt][nt], a[rt & 1], bc[nt].z, bc[nt].w);
                }
            }
        }
#pragma unroll
        for (int nt = 0; nt < 4; nt++) bc[nt] = bn[nt];
    }

    // epilogue: + bias, tanh, pack to half2, store
#pragma unroll
    for (int nt = 0; nt < 4; nt++) {
        const int n0 = ncol0 + nt * 8 + tg * 2;
        const float2 bb = *reinterpret_cast<const float2*>(bias + n0);
#pragma unroll
        for (int rt = 0; rt < 4; rt++) {
            float v0 = tanh_approx(c[rt][nt][0] + bb.x);
            float v1 = tanh_approx(c[rt][nt][1] + bb.y);
            float v2 = tanh_approx(c[rt][nt][2] + bb.x);
            float v3 = tanh_approx(c[rt][nt][3] + bb.y);
            *reinterpret_cast<__half2*>(Out + (rt * 16 + g) * HSTRIDE + n0) =
                __floats2half2_rn(v0, v1);
            *reinterpret_cast<__half2*>(Out + (rt * 16 + g + 8) * HSTRIDE + n0) =
                __floats2half2_rn(v2, v3);
        }
    }
}

// Diagonal of layer 4: out[r] = dot(h3[r,:], W4[:, r]) + b4[r]  (512 threads)
__device__ __forceinline__ void diag_dot(const __half* __restrict__ h3,
                                         const __half* __restrict__ Wt4,
                                         const float* __restrict__ b4,
                                         float* __restrict__ dout) {
    const int t = threadIdx.x;
    const int r = t >> 3, q = t & 7;     // 8 threads per row
    const __half2* hp = reinterpret_cast<const __half2*>(h3 + r * HSTRIDE);
    const __half2* wp = reinterpret_cast<const __half2*>(Wt4 + r * NH);
    float acc = 0.f;
#pragma unroll 8
    for (int j = q * 32; j < q * 32 + 32; j++) {
        float2 hv = __half22float2(hp[j]);
        float2 wv = __half22float2(wp[j]);
        acc = fmaf(hv.x, wv.x, acc);
        acc = fmaf(hv.y, wv.y, acc);
    }
    acc += __shfl_xor_sync(0xFFFFFFFFu, acc, 1);
    acc += __shfl_xor_sync(0xFFFFFFFFu, acc, 2);
    acc += __shfl_xor_sync(0xFFFFFFFFu, acc, 4);
    if (q == 0) dout[r] = acc + b4[r];
}

__device__ __forceinline__ void run_mlp(const __half* zs, __half* buf0, __half* buf1,
                                        const __half2* Wf1, const __half2* Wf2,
                                        const __half2* Wf3, const __half* Wt4,
                                        const float* b1, const float* b2,
                                        const float* b3, const float* b4,
                                        float* dout) {
    mlp_layer<NL, ZSTRIDE>(zs, Wf1, b1, buf1);
    __syncthreads();
    mlp_layer<NH, HSTRIDE>(buf1, Wf2, b2, buf0);
    __syncthreads();
    mlp_layer<NH, HSTRIDE>(buf0, Wf3, b3, buf1);
    __syncthreads();
    diag_dot(buf1, Wt4, b4, dout);
    __syncthreads();
}

__global__ __launch_bounds__(512, 1)
void decoder_kernel(const float* __restrict__ x, const float* __restrict__ koop,
                    const float* __restrict__ sb1, const float* __restrict__ sb2,
                    const float* __restrict__ sb3, const float* __restrict__ sb4,
                    const float* __restrict__ tb1, const float* __restrict__ tb2,
                    const float* __restrict__ tb3, const float* __restrict__ tb4,
                    float* __restrict__ out) {
    extern __shared__ __half smem[];
    __half* zs = smem;                 // 64 x 72
    __half* buf0 = smem + BUF0_OFF;    // 64 x 520
    __half* buf1 = smem + BUF1_OFF;    // 64 x 520
    float* ds = reinterpret_cast<float*>(smem + SMEM_HALVES);
    float* dt = ds + 64;

    const int b = blockIdx.x;
    const float* kb = koop + b * (NL * ND);

    // Load + transpose z: z[d][l] = koopman[b][l][d]
    for (int i = threadIdx.x; i < NL * ND; i += 512) {
        int l = i >> 6, d = i & 63;
        zs[d * ZSTRIDE + l] = __float2half_rn(kb[i]);
    }
    __syncthreads();

    run_mlp(zs, buf0, buf1, g_Wf1[0], g_Wf2[0], g_Wf3[0], g_Wt4[0],
            sb1, sb2, sb3, sb4, ds);
    run_mlp(zs, buf0, buf1, g_Wf1[1], g_Wf2[1], g_Wf3[1], g_Wt4[1],
            tb1, tb2, tb3, tb4, dt);
    __syncthreads();

    if (threadIdx.x < 64) {
        const int r = threadIdx.x;
        out[b * ND + r] = (x[b * ND + r] - dt[r]) * __expf(-ds[r]);
    }
}

extern "C" void kernel_launch(void* const* d_in, const int* in_sizes, int n_in,
                              void* d_out, int out_size) {
    (void)in_sizes; (void)n_in; (void)out_size;
    const float* x   = (const float*)d_in[0];
    const float* kp  = (const float*)d_in[1];
    const float* sW1 = (const float*)d_in[2];
    const float* sb1 = (const float*)d_in[3];
    const float* sW2 = (const float*)d_in[4];
    const float* sb2 = (const float*)d_in[5];
    const float* sW3 = (const float*)d_in[6];
    const float* sb3 = (const float*)d_in[7];
    const float* sW4 = (const float*)d_in[8];
    const float* sb4 = (const float*)d_in[9];
    const float* tW1 = (const float*)d_in[10];
    const float* tb1 = (const float*)d_in[11];
    const float* tW2 = (const float*)d_in[12];
    const float* tb2 = (const float*)d_in[13];
    const float* tW3 = (const float*)d_in[14];
    const float* tb3 = (const float*)d_in[15];
    const float* tW4 = (const float*)d_in[16];
    const float* tb4 = (const float*)d_in[17];
    float* out = (float*)d_out;

    convert_kernel<<<(NH * NH / 2 + 255) / 256, 256>>>(sW1, sW2, sW3, sW4, tW1, tW2, tW3, tW4);

    cudaFuncSetAttribute(decoder_kernel, cudaFuncAttributeMaxDynamicSharedMemorySize, SMEM_BYTES);
    decoder_kernel<<<NB, 512, SMEM_BYTES>>>(x, kp,
                                            sb1, sb2, sb3, sb4,
                                            tb1, tb2, tb3, tb4,
                                            out);
}

// round 9
// speedup vs baseline: 1.7518x; 1.0223x over previous
#include <cuda_runtime.h>
#include <cuda_fp16.h>
#include <math.h>
#include <stdint.h>

// Problem sizes
#define NB 2048
#define ND 64
#define NL 64
#define NH 512

// SMEM layout (in halves)
#define ZSTRIDE 72            // 64 + 8 pad -> conflict-free ldmatrix (144B row stride)
#define HSTRIDE 520           // 512 + 8 pad (1040B row stride)
#define BUF0_OFF (64 * ZSTRIDE)
#define BUF1_OFF (BUF0_OFF + 64 * HSTRIDE)
#define SMEM_HALVES (BUF1_OFF + 64 * HSTRIDE)
#define SMEM_BYTES (SMEM_HALVES * 2 + 2 * 64 * 4 + 16)

// Fragment-major fp16 weights, PAIR-PACKED for LDG.128:
// uint4 index ((n8 * Ks/2 + ks2) * 32 + lane); .xy = kstep 2*ks2 frag (w0,w1),
// .zw = kstep 2*ks2+1 frag. Within a frag: n = n8*8 + (lane>>2),
// k = kstep*16 + (lane&3)*2 + w*8, half2 = (W[k][n], W[k+1][n]).
__device__ __half2 g_Wf1[2][NL * NH / 2];   // Ks = 4
__device__ __half2 g_Wf2[2][NH * NH / 2];   // Ks = 32
__device__ __half2 g_Wf3[2][NH * NH / 2];   // Ks = 32
__device__ __half  g_Wt4[2][ND * NH];       // [n][k] for diagonal dot

__global__ void convert_kernel(const float* __restrict__ sW1, const float* __restrict__ sW2,
                               const float* __restrict__ sW3, const float* __restrict__ sW4,
                               const float* __restrict__ tW1, const float* __restrict__ tW2,
                               const float* __restrict__ tW3, const float* __restrict__ tW4) {
    const int i = blockIdx.x * blockDim.x + threadIdx.x;
    const float* w1[2] = {sW1, tW1};
    const float* w2[2] = {sW2, tW2};
    const float* w3[2] = {sW3, tW3};
    const float* w4[2] = {sW4, tW4};
#pragma unroll
    for (int m = 0; m < 2; m++) {
        if (i < NH * NH / 2) {   // W2/W3: Ks = 32, Ks2 = 16
            const int c = i & 3, w = c & 1, sub = c >> 1;
            const int lane = (i >> 2) & 31, ks2 = (i >> 7) & 15, n8 = i >> 11;
            const int kstep = ks2 * 2 + sub;
            const int n = n8 * 8 + (lane >> 2);
            const int k = kstep * 16 + (lane & 3) * 2 + w * 8;
            g_Wf2[m][i] = __floats2half2_rn(w2[m][k * NH + n], w2[m][(k + 1) * NH + n]);
            g_Wf3[m][i] = __floats2half2_rn(w3[m][k * NH + n], w3[m][(k + 1) * NH + n]);
        }
        if (i < NL * NH / 2) {   // W1: Ks = 4, Ks2 = 2
            const int c = i & 3, w = c & 1, sub = c >> 1;
            const int lane = (i >> 2) & 31, ks2 = (i >> 7) & 1, n8 = i >> 8;
            const int kstep = ks2 * 2 + sub;
            const int n = n8 * 8 + (lane >> 2);
            const int k = kstep * 16 + (lane & 3) * 2 + w * 8;
            g_Wf1[m][i] = __floats2half2_rn(w1[m][k * NH + n], w1[m][(k + 1) * NH + n]);
        }
        if (i < NH * ND) {       // W4 (512,64) row-major -> [n][k]
            const int k = i >> 6, n = i & 63;
            g_Wt4[m][n * NH + k] = __float2half_rn(w4[m][i]);
        }
    }
}

__device__ __forceinline__ float tanh_approx(float x) {
    float y;
    asm("tanh.approx.f32 %0, %1;" : "=f"(y) : "f"(x));
    return y;
}

__device__ __forceinline__ void mma_m16n8k16(float c[4], const uint32_t a[4],
                                             uint32_t b0, uint32_t b1) {
    asm volatile(
        "mma.sync.aligned.m16n8k16.row.col.f32.f16.f16.f32 "
        "{%0,%1,%2,%3}, {%4,%5,%6,%7}, {%8,%9}, {%0,%1,%2,%3};\n"
        : "+f"(c[0]), "+f"(c[1]), "+f"(c[2]), "+f"(c[3])
        : "r"(a[0]), "r"(a[1]), "r"(a[2]), "r"(a[3]), "r"(b0), "r"(b1));
}

__device__ __forceinline__ void ldsm4(uint32_t a[4], uint32_t addr) {
    asm volatile("ldmatrix.sync.aligned.m8n8.x4.shared.b16 {%0,%1,%2,%3}, [%4];"
                 : "=r"(a[0]), "=r"(a[1]), "=r"(a[2]), "=r"(a[3]) : "r"(addr));
}

// One dense layer: Out(64 x 512) = tanh(A(64 x K) @ W(K x 512) + bias)
// 8 warps; warp w owns output columns [w*64, w*64+64) -> 32 MMAs per k-step
// from 4 LDSM + 4 LDG.128-pair fragments (halves L1 ops/MAC vs 32-col warps).
template <int K, int AS>
__device__ __noinline__ void mlp_layer(const __half* __restrict__ A,
                                       const __half2* __restrict__ Wf,
                                       const float* __restrict__ bias,
                                       __half* __restrict__ Out) {
    constexpr int Ks = K / 16;
    constexpr int Ks2 = Ks / 2;
    const int lane = threadIdx.x & 31;
    const int warp = threadIdx.x >> 5;
    const int g = lane >> 2;
    const int tg = lane & 3;
    const int ncol0 = warp * 64;

    // ldmatrix base addresses for the 4 row tiles
    uint32_t abase[4];
    {
        const __half* ap = A + (lane & 15) * AS + ((lane >> 4) << 3);
#pragma unroll
        for (int rt = 0; rt < 4; rt++)
            abase[rt] = (uint32_t)__cvta_generic_to_shared(ap + rt * 16 * AS);
    }

    // B: base pointer for this warp's 8 n8-tiles; nt offsets compile-time
    const uint4* bq = reinterpret_cast<const uint4*>(Wf) + (warp * 8) * (Ks2 * 32) + lane;

    float c[4][8][4];
#pragma unroll
    for (int rt = 0; rt < 4; rt++)
#pragma unroll
        for (int nt = 0; nt < 8; nt++)
#pragma unroll
            for (int r = 0; r < 4; r++) c[rt][nt][r] = 0.f;

    uint4 bc[8], bn[8];
#pragma unroll
    for (int nt = 0; nt < 8; nt++) bc[nt] = bq[nt * (Ks2 * 32)];

#pragma unroll 2
    for (int ks2 = 0; ks2 < Ks2; ks2++) {
        const int kn = (ks2 + 1 < Ks2) ? (ks2 + 1) : (Ks2 - 1);
#pragma unroll
        for (int nt = 0; nt < 8; nt++) bn[nt] = bq[nt * (Ks2 * 32) + kn * 32];

        uint32_t a[4][4];
#pragma unroll
        for (int rt = 0; rt < 4; rt++) ldsm4(a[rt], abase[rt] + (ks2 * 2) * 32);
#pragma unroll
        for (int rt = 0; rt < 4; rt++)
#pragma unroll
            for (int nt = 0; nt < 8; nt++)
                mma_m16n8k16(c[rt][nt], a[rt], bc[nt].x, bc[nt].y);

#pragma unroll
        for (int rt = 0; rt < 4; rt++) ldsm4(a[rt], abase[rt] + (ks2 * 2 + 1) * 32);
#pragma unroll
        for (int rt = 0; rt < 4; rt++)
#pragma unroll
            for (int nt = 0; nt < 8; nt++)
                mma_m16n8k16(c[rt][nt], a[rt], bc[nt].z, bc[nt].w);

#pragma unroll
        for (int nt = 0; nt < 8; nt++) bc[nt] = bn[nt];
    }

    // epilogue: + bias, tanh, pack to half2, store
#pragma unroll
    for (int nt = 0; nt < 8; nt++) {
        const int n0 = ncol0 + nt * 8 + tg * 2;
        const float2 bb = *reinterpret_cast<const float2*>(bias + n0);
#pragma unroll
        for (int rt = 0; rt < 4; rt++) {
            float v0 = tanh_approx(c[rt][nt][0] + bb.x);
            float v1 = tanh_approx(c[rt][nt][1] + bb.y);
            float v2 = tanh_approx(c[rt][nt][2] + bb.x);
            float v3 = tanh_approx(c[rt][nt][3] + bb.y);
            *reinterpret_cast<__half2*>(Out + (rt * 16 + g) * HSTRIDE + n0) =
                __floats2half2_rn(v0, v1);
            *reinterpret_cast<__half2*>(Out + (rt * 16 + g + 8) * HSTRIDE + n0) =
                __floats2half2_rn(v2, v3);
        }
    }
}

// Diagonal of layer 4: out[r] = dot(h3[r,:], W4[:, r]) + b4[r]  (256 threads)
__device__ __forceinline__ void diag_dot(const __half* __restrict__ h3,
                                         const __half* __restrict__ Wt4,
                                         const float* __restrict__ b4,
                                         float* __restrict__ dout) {
    const int t = threadIdx.x;
    const int r = t >> 2, q = t & 3;     // 4 threads per row
    const __half2* hp = reinterpret_cast<const __half2*>(h3 + r * HSTRIDE);
    const __half2* wp = reinterpret_cast<const __half2*>(Wt4 + r * NH);
    float acc = 0.f;
#pragma unroll 8
    for (int j = q * 64; j < q * 64 + 64; j++) {
        float2 hv = __half22float2(hp[j]);
        float2 wv = __half22float2(wp[j]);
        acc = fmaf(hv.x, wv.x, acc);
        acc = fmaf(hv.y, wv.y, acc);
    }
    acc += __shfl_xor_sync(0xFFFFFFFFu, acc, 1);
    acc += __shfl_xor_sync(0xFFFFFFFFu, acc, 2);
    if (q == 0) dout[r] = acc + b4[r];
}

__device__ __forceinline__ void run_mlp(const __half* zs, __half* buf0, __half* buf1,
                                        const __half2* Wf1, const __half2* Wf2,
                                        const __half2* Wf3, const __half* Wt4,
                                        const float* b1, const float* b2,
                                        const float* b3, const float* b4,
                                        float* dout) {
    mlp_layer<NL, ZSTRIDE>(zs, Wf1, b1, buf1);
    __syncthreads();
    mlp_layer<NH, HSTRIDE>(buf1, Wf2, b2, buf0);
    __syncthreads();
    mlp_layer<NH, HSTRIDE>(buf0, Wf3, b3, buf1);
    __syncthreads();
    diag_dot(buf1, Wt4, b4, dout);
    __syncthreads();
}

__global__ __launch_bounds__(256, 1)
void decoder_kernel(const float* __restrict__ x, const float* __restrict__ koop,
                    const float* __restrict__ sb1, const float* __restrict__ sb2,
                    const float* __restrict__ sb3, const float* __restrict__ sb4,
                    const float* __restrict__ tb1, const float* __restrict__ tb2,
                    const float* __restrict__ tb3, const float* __restrict__ tb4,
                    float* __restrict__ out) {
    extern __shared__ __half smem[];
    __half* zs = smem;                 // 64 x 72
    __half* buf0 = smem + BUF0_OFF;    // 64 x 520
    __half* buf1 = smem + BUF1_OFF;    // 64 x 520
    float* ds = reinterpret_cast<float*>(smem + SMEM_HALVES);
    float* dt = ds + 64;

    const int b = blockIdx.x;
    const float* kb = koop + b * (NL * ND);

    // Load + transpose z: z[d][l] = koopman[b][l][d]
    for (int i = threadIdx.x; i < NL * ND; i += 256) {
        int l = i >> 6, d = i & 63;
        zs[d * ZSTRIDE + l] = __float2half_rn(kb[i]);
    }
    __syncthreads();

    run_mlp(zs, buf0, buf1, g_Wf1[0], g_Wf2[0], g_Wf3[0], g_Wt4[0],
            sb1, sb2, sb3, sb4, ds);
    run_mlp(zs, buf0, buf1, g_Wf1[1], g_Wf2[1], g_Wf3[1], g_Wt4[1],
            tb1, tb2, tb3, tb4, dt);
    __syncthreads();

    if (threadIdx.x < 64) {
        const int r = threadIdx.x;
        out[b * ND + r] = (x[b * ND + r] - dt[r]) * __expf(-ds[r]);
    }
}

extern "C" void kernel_launch(void* const* d_in, const int* in_sizes, int n_in,
                              void* d_out, int out_size) {
    (void)in_sizes; (void)n_in; (void)out_size;
    const float* x   = (const float*)d_in[0];
    const float* kp  = (const float*)d_in[1];
    const float* sW1 = (const float*)d_in[2];
    const float* sb1 = (const float*)d_in[3];
    const float* sW2 = (const float*)d_in[4];
    const float* sb2 = (const float*)d_in[5];
    const float* sW3 = (const float*)d_in[6];
    const float* sb3 = (const float*)d_in[7];
    const float* sW4 = (const float*)d_in[8];
    const float* sb4 = (const float*)d_in[9];
    const float* tW1 = (const float*)d_in[10];
    const float* tb1 = (const float*)d_in[11];
    const float* tW2 = (const float*)d_in[12];
    const float* tb2 = (const float*)d_in[13];
    const float* tW3 = (const float*)d_in[14];
    const float* tb3 = (const float*)d_in[15];
    const float* tW4 = (const float*)d_in[16];
    const float* tb4 = (const float*)d_in[17];
    float* out = (float*)d_out;

    convert_kernel<<<(NH * NH / 2 + 255) / 256, 256>>>(sW1, sW2, sW3, sW4, tW1, tW2, tW3, tW4);

    cudaFuncSetAttribute(decoder_kernel, cudaFuncAttributeMaxDynamicSharedMemorySize, SMEM_BYTES);
    decoder_kernel<<<NB, 256, SMEM_BYTES>>>(x, kp,
                                            sb1, sb2, sb3, sb4,
                                            tb1, tb2, tb3, tb4,
                                            out);
}

// round 11
// speedup vs baseline: 2.3871x; 1.3627x over previous
#include <cuda_runtime.h>
#include <cuda_fp16.h>
#include <math.h>
#include <stdint.h>

// Problem sizes
#define NB 2048
#define ND 64
#define NL 64
#define NH 512

// SMEM layout (in halves)
#define ZSTRIDE 72            // 64 + 8 pad -> conflict-free ldmatrix (144B row stride)
#define HSTRIDE 520           // 512 + 8 pad (1040B row stride)
#define BUF0_OFF (64 * ZSTRIDE)
#define BUF1_OFF (BUF0_OFF + 64 * HSTRIDE)
#define SMEM_HALVES (BUF1_OFF + 64 * HSTRIDE)
#define SMEM_BYTES (SMEM_HALVES * 2 + 2 * 64 * 4 + 16)

// Fragment-major fp16 weights, PAIR-PACKED for LDG.128:
// uint4 index ((n8 * Ks/2 + ks2) * 32 + lane); .xy = kstep 2*ks2 frag (w0,w1),
// .zw = kstep 2*ks2+1 frag. Within a frag: n = n8*8 + (lane>>2),
// k = kstep*16 + (lane&3)*2 + w*8, half2 = (W[k][n], W[k+1][n]).
__device__ __half2 g_Wf1[2][NL * NH / 2];   // Ks = 4
__device__ __half2 g_Wf2[2][NH * NH / 2];   // Ks = 32
__device__ __half2 g_Wf3[2][NH * NH / 2];   // Ks = 32
// W4 packed to match the mma.m16n8 accumulator layout:
// j = ((((w*4+rt)*8+nt)*2+p)*32+lane); value = half2(W4[n0][r], W4[n0+1][r])
// with n0 = w*64+nt*8+(lane&3)*2, r = rt*16+(lane>>2)+p*8.
__device__ __half2 g_W4f[2][ND * NH / 2];   // 16384 half2

__global__ void convert_kernel(const float* __restrict__ sW1, const float* __restrict__ sW2,
                               const float* __restrict__ sW3, const float* __restrict__ sW4,
                               const float* __restrict__ tW1, const float* __restrict__ tW2,
                               const float* __restrict__ tW3, const float* __restrict__ tW4) {
    const int i = blockIdx.x * blockDim.x + threadIdx.x;
    const float* w1[2] = {sW1, tW1};
    const float* w2[2] = {sW2, tW2};
    const float* w3[2] = {sW3, tW3};
    const float* w4[2] = {sW4, tW4};
#pragma unroll
    for (int m = 0; m < 2; m++) {
        if (i < NH * NH / 2) {   // W2/W3: Ks = 32, Ks2 = 16
            const int c = i & 3, w = c & 1, sub = c >> 1;
            const int lane = (i >> 2) & 31, ks2 = (i >> 7) & 15, n8 = i >> 11;
            const int kstep = ks2 * 2 + sub;
            const int n = n8 * 8 + (lane >> 2);
            const int k = kstep * 16 + (lane & 3) * 2 + w * 8;
            g_Wf2[m][i] = __floats2half2_rn(w2[m][k * NH + n], w2[m][(k + 1) * NH + n]);
            g_Wf3[m][i] = __floats2half2_rn(w3[m][k * NH + n], w3[m][(k + 1) * NH + n]);
        }
        if (i < NL * NH / 2) {   // W1: Ks = 4, Ks2 = 2
            const int c = i & 3, w = c & 1, sub = c >> 1;
            const int lane = (i >> 2) & 31, ks2 = (i >> 7) & 1, n8 = i >> 8;
            const int kstep = ks2 * 2 + sub;
            const int n = n8 * 8 + (lane >> 2);
            const int k = kstep * 16 + (lane & 3) * 2 + w * 8;
            g_Wf1[m][i] = __floats2half2_rn(w1[m][k * NH + n], w1[m][(k + 1) * NH + n]);
        }
        if (i < ND * NH / 2) {   // W4 (512,64) -> accumulator-matched fragments
            const int lane = i & 31, p = (i >> 5) & 1, nt = (i >> 6) & 7;
            const int rt = (i >> 9) & 3, w = i >> 11;
            const int tg = lane & 3, g = lane >> 2;
            const int n0 = w * 64 + nt * 8 + tg * 2;
            const int r = rt * 16 + g + p * 8;
            g_W4f[m][i] = __floats2half2_rn(w4[m][n0 * ND + r], w4[m][(n0 + 1) * ND + r]);
        }
    }
}

__device__ __forceinline__ float tanh_approx(float x) {
    float y;
    asm("tanh.approx.f32 %0, %1;" : "=f"(y) : "f"(x));
    return y;
}

__device__ __forceinline__ void mma_m16n8k16(float c[4], const uint32_t a[4],
                                             uint32_t b0, uint32_t b1) {
    asm volatile(
        "mma.sync.aligned.m16n8k16.row.col.f32.f16.f16.f32 "
        "{%0,%1,%2,%3}, {%4,%5,%6,%7}, {%8,%9}, {%0,%1,%2,%3};\n"
        : "+f"(c[0]), "+f"(c[1]), "+f"(c[2]), "+f"(c[3])
        : "r"(a[0]), "r"(a[1]), "r"(a[2]), "r"(a[3]), "r"(b0), "r"(b1));
}

__device__ __forceinline__ void ldsm4(uint32_t a[4], uint32_t addr) {
    asm volatile("ldmatrix.sync.aligned.m8n8.x4.shared.b16 {%0,%1,%2,%3}, [%4];"
                 : "=r"(a[0]), "=r"(a[1]), "=r"(a[2]), "=r"(a[3]) : "r"(addr));
}

// One dense layer: Out(64 x 512) = tanh(A(64 x K) @ W(K x 512) + bias)
// 8 warps; warp w owns output columns [w*64, w*64+64).
template <int K, int AS>
__device__ __noinline__ void mlp_layer(const __half* __restrict__ A,
                                       const __half2* __restrict__ Wf,
                                       const float* __restrict__ bias,
                                       __half* __restrict__ Out) {
    constexpr int Ks = K / 16;
    constexpr int Ks2 = Ks / 2;
    const int lane = threadIdx.x & 31;
    const int warp = threadIdx.x >> 5;
    const int g = lane >> 2;
    const int tg = lane & 3;
    const int ncol0 = warp * 64;

    uint32_t abase[4];
    {
        const __half* ap = A + (lane & 15) * AS + ((lane >> 4) << 3);
#pragma unroll
        for (int rt = 0; rt < 4; rt++)
            abase[rt] = (uint32_t)__cvta_generic_to_shared(ap + rt * 16 * AS);
    }

    const uint4* bq = reinterpret_cast<const uint4*>(Wf) + (warp * 8) * (Ks2 * 32) + lane;

    float c[4][8][4];
#pragma unroll
    for (int rt = 0; rt < 4; rt++)
#pragma unroll
        for (int nt = 0; nt < 8; nt++)
#pragma unroll
            for (int r = 0; r < 4; r++) c[rt][nt][r] = 0.f;

    uint4 bc[8], bn[8];
#pragma unroll
    for (int nt = 0; nt < 8; nt++) bc[nt] = bq[nt * (Ks2 * 32)];

#pragma unroll 2
    for (int ks2 = 0; ks2 < Ks2; ks2++) {
        const int kn = (ks2 + 1 < Ks2) ? (ks2 + 1) : (Ks2 - 1);
#pragma unroll
        for (int nt = 0; nt < 8; nt++) bn[nt] = bq[nt * (Ks2 * 32) + kn * 32];

        uint32_t a[4][4];
#pragma unroll
        for (int rt = 0; rt < 4; rt++) ldsm4(a[rt], abase[rt] + (ks2 * 2) * 32);
#pragma unroll
        for (int rt = 0; rt < 4; rt++)
#pragma unroll
            for (int nt = 0; nt < 8; nt++)
                mma_m16n8k16(c[rt][nt], a[rt], bc[nt].x, bc[nt].y);

#pragma unroll
        for (int rt = 0; rt < 4; rt++) ldsm4(a[rt], abase[rt] + (ks2 * 2 + 1) * 32);
#pragma unroll
        for (int rt = 0; rt < 4; rt++)
#pragma unroll
            for (int nt = 0; nt < 8; nt++)
                mma_m16n8k16(c[rt][nt], a[rt], bc[nt].z, bc[nt].w);

#pragma unroll
        for (int nt = 0; nt < 8; nt++) bc[nt] = bn[nt];
    }

    // epilogue: + bias, tanh, pack to half2, store
#pragma unroll
    for (int nt = 0; nt < 8; nt++) {
        const int n0 = ncol0 + nt * 8 + tg * 2;
        const float2 bb = *reinterpret_cast<const float2*>(bias + n0);
#pragma unroll
        for (int rt = 0; rt < 4; rt++) {
            float v0 = tanh_approx(c[rt][nt][0] + bb.x);
            float v1 = tanh_approx(c[rt][nt][1] + bb.y);
            float v2 = tanh_approx(c[rt][nt][2] + bb.x);
            float v3 = tanh_approx(c[rt][nt][3] + bb.y);
            *reinterpret_cast<__half2*>(Out + (rt * 16 + g) * HSTRIDE + n0) =
                __floats2half2_rn(v0, v1);
            *reinterpret_cast<__half2*>(Out + (rt * 16 + g + 8) * HSTRIDE + n0) =
                __floats2half2_rn(v2, v3);
        }
    }
}

// Layer 3 fused with the layer-4 diagonal: instead of storing tanh(h3),
// multiply by W4 fragments and write per-warp row partials to partsm[8][64].
__device__ __noinline__ void mlp_layer_diag(const __half* __restrict__ A,
                                            const __half2* __restrict__ Wf,
                                            const float* __restrict__ bias,
                                            const __half2* __restrict__ W4f,
                                            float* __restrict__ partsm) {
    constexpr int Ks = NH / 16;
    constexpr int Ks2 = Ks / 2;
    const int lane = threadIdx.x & 31;
    const int warp = threadIdx.x >> 5;
    const int g = lane >> 2;
    const int tg = lane & 3;
    const int ncol0 = warp * 64;

    uint32_t abase[4];
    {
        const __half* ap = A + (lane & 15) * HSTRIDE + ((lane >> 4) << 3);
#pragma unroll
        for (int rt = 0; rt < 4; rt++)
            abase[rt] = (uint32_t)__cvta_generic_to_shared(ap + rt * 16 * HSTRIDE);
    }

    const uint4* bq = reinterpret_cast<const uint4*>(Wf) + (warp * 8) * (Ks2 * 32) + lane;

    float c[4][8][4];
#pragma unroll
    for (int rt = 0; rt < 4; rt++)
#pragma unroll
        for (int nt = 0; nt < 8; nt++)
#pragma unroll
            for (int r = 0; r < 4; r++) c[rt][nt][r] = 0.f;

    uint4 bc[8], bn[8];
#pragma unroll
    for (int nt = 0; nt < 8; nt++) bc[nt] = bq[nt * (Ks2 * 32)];

#pragma unroll 2
    for (int ks2 = 0; ks2 < Ks2; ks2++) {
        const int kn = (ks2 + 1 < Ks2) ? (ks2 + 1) : (Ks2 - 1);
#pragma unroll
        for (int nt = 0; nt < 8; nt++) bn[nt] = bq[nt * (Ks2 * 32) + kn * 32];

        uint32_t a[4][4];
#pragma unroll
        for (int rt = 0; rt < 4; rt++) ldsm4(a[rt], abase[rt] + (ks2 * 2) * 32);
#pragma unroll
        for (int rt = 0; rt < 4; rt++)
#pragma unroll
            for (int nt = 0; nt < 8; nt++)
                mma_m16n8k16(c[rt][nt], a[rt], bc[nt].x, bc[nt].y);

#pragma unroll
        for (int rt = 0; rt < 4; rt++) ldsm4(a[rt], abase[rt] + (ks2 * 2 + 1) * 32);
#pragma unroll
        for (int rt = 0; rt < 4; rt++)
#pragma unroll
            for (int nt = 0; nt < 8; nt++)
                mma_m16n8k16(c[rt][nt], a[rt], bc[nt].z, bc[nt].w);

#pragma unroll
        for (int nt = 0; nt < 8; nt++) bc[nt] = bn[nt];
    }

    // fused epilogue: tanh then dot with W4 fragments -> row partials
    const __half2* wb = W4f + warp * 2048 + lane;   // [rt][nt][p] stride 32
    float part[4][2];
#pragma unroll
    for (int rt = 0; rt < 4; rt++) { part[rt][0] = 0.f; part[rt][1] = 0.f; }

#pragma unroll
    for (int nt = 0; nt < 8; nt++) {
        const int n0 = ncol0 + nt * 8 + tg * 2;
        const float2 bb = *reinterpret_cast<const float2*>(bias + n0);
#pragma unroll
        for (int rt = 0; rt < 4; rt++) {
            const float t0 = tanh_approx(c[rt][nt][0] + bb.x);
            const float t1 = tanh_approx(c[rt][nt][1] + bb.y);
            const float t2 = tanh_approx(c[rt][nt][2] + bb.x);
            const float t3 = tanh_approx(c[rt][nt][3] + bb.y);
            const float2 wA = __half22float2(wb[((rt * 8 + nt) * 2 + 0) * 32]);
            const float2 wB = __half22float2(wb[((rt * 8 + nt) * 2 + 1) * 32]);
            part[rt][0] = fmaf(t0, wA.x, fmaf(t1, wA.y, part[rt][0]));
            part[rt][1] = fmaf(t2, wB.x, fmaf(t3, wB.y, part[rt][1]));
        }
    }

    // reduce over tg (4 lanes share a row-partial), store per-warp partials
#pragma unroll
    for (int rt = 0; rt < 4; rt++) {
#pragma unroll
        for (int p = 0; p < 2; p++) {
            float v = part[rt][p];
            v += __shfl_xor_sync(0xFFFFFFFFu, v, 1);
            v += __shfl_xor_sync(0xFFFFFFFFu, v, 2);
            if (tg == 0) partsm[warp * 64 + rt * 16 + p * 8 + g] = v;
        }
    }
}

__device__ __forceinline__ void run_mlp(const __half* zs, __half* buf0, __half* buf1,
                                        const __half2* Wf1, const __half2* Wf2,
                                        const __half2* Wf3, const __half2* W4f,
                                        const float* b1, const float* b2,
                                        const float* b3, const float* b4,
                                        float* partsm, float* dout) {
    mlp_layer<NL, ZSTRIDE>(zs, Wf1, b1, buf1);
    __syncthreads();
    mlp_layer<NH, HSTRIDE>(buf1, Wf2, b2, buf0);
    __syncthreads();
    mlp_layer_diag(buf0, Wf3, b3, W4f, partsm);
    __syncthreads();
    if (threadIdx.x < 64) {
        const int r = threadIdx.x;
        float s = 0.f;
#pragma unroll
        for (int w = 0; w < 8; w++) s += partsm[w * 64 + r];
        dout[r] = s + b4[r];
    }
    __syncthreads();
}

__global__ __launch_bounds__(256, 1)
void decoder_kernel(const float* __restrict__ x, const float* __restrict__ koop,
                    const float* __restrict__ sb1, const float* __restrict__ sb2,
                    const float* __restrict__ sb3, const float* __restrict__ sb4,
                    const float* __restrict__ tb1, const float* __restrict__ tb2,
                    const float* __restrict__ tb3, const float* __restrict__ tb4,
                    float* __restrict__ out) {
    extern __shared__ __half smem[];
    __half* zs = smem;                 // 64 x 72
    __half* buf0 = smem + BUF0_OFF;    // 64 x 520
    __half* buf1 = smem + BUF1_OFF;    // 64 x 520 (free during layer3 -> partials)
    float* ds = reinterpret_cast<float*>(smem + SMEM_HALVES);
    float* dt = ds + 64;
    float* partsm = reinterpret_cast<float*>(buf1);   // 8 x 64 f32 partials

    const int b = blockIdx.x;
    const float* kb = koop + b * (NL * ND);

    // Load + transpose z: z[d][l] = koopman[b][l][d]
    for (int i = threadIdx.x; i < NL * ND; i += 256) {
        int l = i >> 6, d = i & 63;
        zs[d * ZSTRIDE + l] = __float2half_rn(kb[i]);
    }
    __syncthreads();

    run_mlp(zs, buf0, buf1, g_Wf1[0], g_Wf2[0], g_Wf3[0], g_W4f[0],
            sb1, sb2, sb3, sb4, partsm, ds);
    run_mlp(zs, buf0, buf1, g_Wf1[1], g_Wf2[1], g_Wf3[1], g_W4f[1],
            tb1, tb2, tb3, tb4, partsm, dt);

    if (threadIdx.x < 64) {
        const int r = threadIdx.x;
        out[b * ND + r] = (x[b * ND + r] - dt[r]) * __expf(-ds[r]);
    }
}

extern "C" void kernel_launch(void* const* d_in, const int* in_sizes, int n_in,
                              void* d_out, int out_size) {
    (void)in_sizes; (void)n_in; (void)out_size;
    const float* x   = (const float*)d_in[0];
    const float* kp  = (const float*)d_in[1];
    const float* sW1 = (const float*)d_in[2];
    const float* sb1 = (const float*)d_in[3];
    const float* sW2 = (const float*)d_in[4];
    const float* sb2 = (const float*)d_in[5];
    const float* sW3 = (const float*)d_in[6];
    const float* sb3 = (const float*)d_in[7];
    const float* sW4 = (const float*)d_in[8];
    const float* sb4 = (const float*)d_in[9];
    const float* tW1 = (const float*)d_in[10];
    const float* tb1 = (const float*)d_in[11];
    const float* tW2 = (const float*)d_in[12];
    const float* tb2 = (const float*)d_in[13];
    const float* tW3 = (const float*)d_in[14];
    const float* tb3 = (const float*)d_in[15];
    const float* tW4 = (const float*)d_in[16];
    const float* tb4 = (const float*)d_in[17];
    float* out = (float*)d_out;

    convert_kernel<<<(NH * NH / 2 + 255) / 256, 256>>>(sW1, sW2, sW3, sW4, tW1, tW2, tW3, tW4);

    cudaFuncSetAttribute(decoder_kernel, cudaFuncAttributeMaxDynamicSharedMemorySize, SMEM_BYTES);
    decoder_kernel<<<NB, 256, SMEM_BYTES>>>(x, kp,
                                            sb1, sb2, sb3, sb4,
                                            tb1, tb2, tb3, tb4,
                                            out);
}

// round 12
// speedup vs baseline: 2.5669x; 1.0753x over previous
#include <cuda_runtime.h>
#include <cuda_fp16.h>
#include <math.h>
#include <stdint.h>

// Problem sizes
#define NB 2048
#define ND 64
#define NL 64
#define NH 512
#define MR 32                 // rows per CTA (half a batch element)

// SMEM layout (in halves)
#define ZSTRIDE 72            // 64 + 8 pad -> conflict-free ldmatrix
#define HSTRIDE 520           // 512 + 8 pad
#define BUF0_OFF (MR * ZSTRIDE)
#define BUF1_OFF (BUF0_OFF + MR * HSTRIDE)
#define SMEM_HALVES (BUF1_OFF + MR * HSTRIDE)
// after halves: ds[32] f32, dt[32] f32, partials[8*32] f32
#define SMEM_BYTES (SMEM_HALVES * 2 + (2 * MR + 8 * MR) * 4 + 16)

// Fragment-major fp16 weights, PAIR-PACKED for LDG.128 (same layout as r11):
__device__ __half2 g_Wf1[2][NL * NH / 2];   // Ks = 4
__device__ __half2 g_Wf2[2][NH * NH / 2];   // Ks = 32
__device__ __half2 g_Wf3[2][NH * NH / 2];   // Ks = 32
// W4 packed to match mma accumulator layout:
// j = ((((w*4+rt)*8+nt)*2+p)*32+lane); half2(W4[n0][r], W4[n0+1][r]),
// n0 = w*64+nt*8+(lane&3)*2, r = rt*16+(lane>>2)+p*8   (rt is GLOBAL 0..3)
__device__ __half2 g_W4f[2][ND * NH / 2];

__global__ void convert_kernel(const float* __restrict__ sW1, const float* __restrict__ sW2,
                               const float* __restrict__ sW3, const float* __restrict__ sW4,
                               const float* __restrict__ tW1, const float* __restrict__ tW2,
                               const float* __restrict__ tW3, const float* __restrict__ tW4) {
    const int i = blockIdx.x * blockDim.x + threadIdx.x;
    const float* w1[2] = {sW1, tW1};
    const float* w2[2] = {sW2, tW2};
    const float* w3[2] = {sW3, tW3};
    const float* w4[2] = {sW4, tW4};
#pragma unroll
    for (int m = 0; m < 2; m++) {
        if (i < NH * NH / 2) {   // W2/W3: Ks = 32, Ks2 = 16
            const int c = i & 3, w = c & 1, sub = c >> 1;
            const int lane = (i >> 2) & 31, ks2 = (i >> 7) & 15, n8 = i >> 11;
            const int kstep = ks2 * 2 + sub;
            const int n = n8 * 8 + (lane >> 2);
            const int k = kstep * 16 + (lane & 3) * 2 + w * 8;
            g_Wf2[m][i] = __floats2half2_rn(w2[m][k * NH + n], w2[m][(k + 1) * NH + n]);
            g_Wf3[m][i] = __floats2half2_rn(w3[m][k * NH + n], w3[m][(k + 1) * NH + n]);
        }
        if (i < NL * NH / 2) {   // W1: Ks = 4, Ks2 = 2
            const int c = i & 3, w = c & 1, sub = c >> 1;
            const int lane = (i >> 2) & 31, ks2 = (i >> 7) & 1, n8 = i >> 8;
            const int kstep = ks2 * 2 + sub;
            const int n = n8 * 8 + (lane >> 2);
            const int k = kstep * 16 + (lane & 3) * 2 + w * 8;
            g_Wf1[m][i] = __floats2half2_rn(w1[m][k * NH + n], w1[m][(k + 1) * NH + n]);
        }
        if (i < ND * NH / 2) {   // W4 (512,64) -> accumulator-matched fragments
            const int lane = i & 31, p = (i >> 5) & 1, nt = (i >> 6) & 7;
            const int rt = (i >> 9) & 3, w = i >> 11;
            const int tg = lane & 3, g = lane >> 2;
            const int n0 = w * 64 + nt * 8 + tg * 2;
            const int r = rt * 16 + g + p * 8;
            g_W4f[m][i] = __floats2half2_rn(w4[m][n0 * ND + r], w4[m][(n0 + 1) * ND + r]);
        }
    }
}

__device__ __forceinline__ float tanh_approx(float x) {
    float y;
    asm("tanh.approx.f32 %0, %1;" : "=f"(y) : "f"(x));
    return y;
}

__device__ __forceinline__ void mma_m16n8k16(float c[4], const uint32_t a[4],
                                             uint32_t b0, uint32_t b1) {
    asm volatile(
        "mma.sync.aligned.m16n8k16.row.col.f32.f16.f16.f32 "
        "{%0,%1,%2,%3}, {%4,%5,%6,%7}, {%8,%9}, {%0,%1,%2,%3};\n"
        : "+f"(c[0]), "+f"(c[1]), "+f"(c[2]), "+f"(c[3])
        : "r"(a[0]), "r"(a[1]), "r"(a[2]), "r"(a[3]), "r"(b0), "r"(b1));
}

__device__ __forceinline__ void ldsm4(uint32_t a[4], uint32_t addr) {
    asm volatile("ldmatrix.sync.aligned.m8n8.x4.shared.b16 {%0,%1,%2,%3}, [%4];"
                 : "=r"(a[0]), "=r"(a[1]), "=r"(a[2]), "=r"(a[3]) : "r"(addr));
}

// One dense layer: Out(32 x 512) = tanh(A(32 x K) @ W(K x 512) + bias)
// 8 warps; warp w owns output columns [w*64, w*64+64); 2 row tiles (M=32).
template <int K, int AS>
__device__ __noinline__ void mlp_layer(const __half* __restrict__ A,
                                       const __half2* __restrict__ Wf,
                                       const float* __restrict__ bias,
                                       __half* __restrict__ Out) {
    constexpr int Ks = K / 16;
    constexpr int Ks2 = Ks / 2;
    const int lane = threadIdx.x & 31;
    const int warp = threadIdx.x >> 5;
    const int g = lane >> 2;
    const int tg = lane & 3;
    const int ncol0 = warp * 64;

    uint32_t abase[2];
    {
        const __half* ap = A + (lane & 15) * AS + ((lane >> 4) << 3);
#pragma unroll
        for (int rt = 0; rt < 2; rt++)
            abase[rt] = (uint32_t)__cvta_generic_to_shared(ap + rt * 16 * AS);
    }

    const uint4* bq = reinterpret_cast<const uint4*>(Wf) + (warp * 8) * (Ks2 * 32) + lane;

    float c[2][8][4];
#pragma unroll
    for (int rt = 0; rt < 2; rt++)
#pragma unroll
        for (int nt = 0; nt < 8; nt++)
#pragma unroll
            for (int r = 0; r < 4; r++) c[rt][nt][r] = 0.f;

#pragma unroll 2
    for (int ks2 = 0; ks2 < Ks2; ks2++) {
        uint4 bc[8];
#pragma unroll
        for (int nt = 0; nt < 8; nt++) bc[nt] = bq[nt * (Ks2 * 32) + ks2 * 32];

        uint32_t a[2][4];
#pragma unroll
        for (int rt = 0; rt < 2; rt++) ldsm4(a[rt], abase[rt] + (ks2 * 2) * 32);
#pragma unroll
        for (int rt = 0; rt < 2; rt++)
#pragma unroll
            for (int nt = 0; nt < 8; nt++)
                mma_m16n8k16(c[rt][nt], a[rt], bc[nt].x, bc[nt].y);

#pragma unroll
        for (int rt = 0; rt < 2; rt++) ldsm4(a[rt], abase[rt] + (ks2 * 2 + 1) * 32);
#pragma unroll
        for (int rt = 0; rt < 2; rt++)
#pragma unroll
            for (int nt = 0; nt < 8; nt++)
                mma_m16n8k16(c[rt][nt], a[rt], bc[nt].z, bc[nt].w);
    }

    // epilogue: + bias, tanh, pack to half2, store
#pragma unroll
    for (int nt = 0; nt < 8; nt++) {
        const int n0 = ncol0 + nt * 8 + tg * 2;
        const float2 bb = *reinterpret_cast<const float2*>(bias + n0);
#pragma unroll
        for (int rt = 0; rt < 2; rt++) {
            float v0 = tanh_approx(c[rt][nt][0] + bb.x);
            float v1 = tanh_approx(c[rt][nt][1] + bb.y);
            float v2 = tanh_approx(c[rt][nt][2] + bb.x);
            float v3 = tanh_approx(c[rt][nt][3] + bb.y);
            *reinterpret_cast<__half2*>(Out + (rt * 16 + g) * HSTRIDE + n0) =
                __floats2half2_rn(v0, v1);
            *reinterpret_cast<__half2*>(Out + (rt * 16 + g + 8) * HSTRIDE + n0) =
                __floats2half2_rn(v2, v3);
        }
    }
}

// Layer 3 fused with the layer-4 diagonal (M=32; global row = half*32 + local).
__device__ __noinline__ void mlp_layer_diag(const __half* __restrict__ A,
                                            const __half2* __restrict__ Wf,
                                            const float* __restrict__ bias,
                                            const __half2* __restrict__ W4f,
                                            int half,
                                            float* __restrict__ partsm) {
    constexpr int Ks = NH / 16;
    constexpr int Ks2 = Ks / 2;
    const int lane = threadIdx.x & 31;
    const int warp = threadIdx.x >> 5;
    const int g = lane >> 2;
    const int tg = lane & 3;
    const int ncol0 = warp * 64;

    uint32_t abase[2];
    {
        const __half* ap = A + (lane & 15) * HSTRIDE + ((lane >> 4) << 3);
#pragma unroll
        for (int rt = 0; rt < 2; rt++)
            abase[rt] = (uint32_t)__cvta_generic_to_shared(ap + rt * 16 * HSTRIDE);
    }

    const uint4* bq = reinterpret_cast<const uint4*>(Wf) + (warp * 8) * (Ks2 * 32) + lane;

    float c[2][8][4];
#pragma unroll
    for (int rt = 0; rt < 2; rt++)
#pragma unroll
        for (int nt = 0; nt < 8; nt++)
#pragma unroll
            for (int r = 0; r < 4; r++) c[rt][nt][r] = 0.f;

#pragma unroll 2
    for (int ks2 = 0; ks2 < Ks2; ks2++) {
        uint4 bc[8];
#pragma unroll
        for (int nt = 0; nt < 8; nt++) bc[nt] = bq[nt * (Ks2 * 32) + ks2 * 32];

        uint32_t a[2][4];
#pragma unroll
        for (int rt = 0; rt < 2; rt++) ldsm4(a[rt], abase[rt] + (ks2 * 2) * 32);
#pragma unroll
        for (int rt = 0; rt < 2; rt++)
#pragma unroll
            for (int nt = 0; nt < 8; nt++)
                mma_m16n8k16(c[rt][nt], a[rt], bc[nt].x, bc[nt].y);

#pragma unroll
        for (int rt = 0; rt < 2; rt++) ldsm4(a[rt], abase[rt] + (ks2 * 2 + 1) * 32);
#pragma unroll
        for (int rt = 0; rt < 2; rt++)
#pragma unroll
            for (int nt = 0; nt < 8; nt++)
                mma_m16n8k16(c[rt][nt], a[rt], bc[nt].z, bc[nt].w);
    }

    // fused epilogue: tanh then dot with W4 fragments -> row partials
    const __half2* wb = W4f + warp * 2048 + lane;
    float part[2][2];
#pragma unroll
    for (int rt = 0; rt < 2; rt++) { part[rt][0] = 0.f; part[rt][1] = 0.f; }

#pragma unroll
    for (int nt = 0; nt < 8; nt++) {
        const int n0 = ncol0 + nt * 8 + tg * 2;
        const float2 bb = *reinterpret_cast<const float2*>(bias + n0);
#pragma unroll
        for (int rt = 0; rt < 2; rt++) {
            const int rtg = half * 2 + rt;     // global row tile
            const float t0 = tanh_approx(c[rt][nt][0] + bb.x);
            const float t1 = tanh_approx(c[rt][nt][1] + bb.y);
            const float t2 = tanh_approx(c[rt][nt][2] + bb.x);
            const float t3 = tanh_approx(c[rt][nt][3] + bb.y);
            const float2 wA = __half22float2(wb[((rtg * 8 + nt) * 2 + 0) * 32]);
            const float2 wB = __half22float2(wb[((rtg * 8 + nt) * 2 + 1) * 32]);
            part[rt][0] = fmaf(t0, wA.x, fmaf(t1, wA.y, part[rt][0]));
            part[rt][1] = fmaf(t2, wB.x, fmaf(t3, wB.y, part[rt][1]));
        }
    }

#pragma unroll
    for (int rt = 0; rt < 2; rt++) {
#pragma unroll
        for (int p = 0; p < 2; p++) {
            float v = part[rt][p];
            v += __shfl_xor_sync(0xFFFFFFFFu, v, 1);
            v += __shfl_xor_sync(0xFFFFFFFFu, v, 2);
            if (tg == 0) partsm[warp * MR + rt * 16 + p * 8 + g] = v;
        }
    }
}

__device__ __forceinline__ void run_mlp(const __half* zs, __half* buf0, __half* buf1,
                                        const __half2* Wf1, const __half2* Wf2,
                                        const __half2* Wf3, const __half2* W4f,
                                        const float* b1, const float* b2,
                                        const float* b3, const float* b4,
                                        int half, float* partsm, float* dout) {
    mlp_layer<NL, ZSTRIDE>(zs, Wf1, b1, buf1);
    __syncthreads();
    mlp_layer<NH, HSTRIDE>(buf1, Wf2, b2, buf0);
    __syncthreads();
    mlp_layer_diag(buf0, Wf3, b3, W4f, half, partsm);
    __syncthreads();
    if (threadIdx.x < MR) {
        const int r = threadIdx.x;
        float s = 0.f;
#pragma unroll
        for (int w = 0; w < 8; w++) s += partsm[w * MR + r];
        dout[r] = s + b4[half * MR + r];
    }
    __syncthreads();
}

__global__ __launch_bounds__(256, 2)
void decoder_kernel(const float* __restrict__ x, const float* __restrict__ koop,
                    const float* __restrict__ sb1, const float* __restrict__ sb2,
                    const float* __restrict__ sb3, const float* __restrict__ sb4,
                    const float* __restrict__ tb1, const float* __restrict__ tb2,
                    const float* __restrict__ tb3, const float* __restrict__ tb4,
                    float* __restrict__ out) {
    extern __shared__ __half smem[];
    __half* zs = smem;                 // 32 x 72
    __half* buf0 = smem + BUF0_OFF;    // 32 x 520
    __half* buf1 = smem + BUF1_OFF;    // 32 x 520
    float* ds = reinterpret_cast<float*>(smem + SMEM_HALVES);
    float* dt = ds + MR;
    float* partsm = dt + MR;           // 8 x 32 f32 partials

    const int b = blockIdx.x >> 1;
    const int half = blockIdx.x & 1;
    const float* kb = koop + b * (NL * ND);

    // Load + transpose z rows [half*32, half*32+32): zs[d_local][l] = koop[b][l][d]
    for (int i = threadIdx.x; i < NL * MR; i += 256) {
        const int l = i >> 5, dl = i & (MR - 1);
        zs[dl * ZSTRIDE + l] = __float2half_rn(kb[l * ND + half * MR + dl]);
    }
    __syncthreads();

    run_mlp(zs, buf0, buf1, g_Wf1[0], g_Wf2[0], g_Wf3[0], g_W4f[0],
            sb1, sb2, sb3, sb4, half, partsm, ds);
    run_mlp(zs, buf0, buf1, g_Wf1[1], g_Wf2[1], g_Wf3[1], g_W4f[1],
            tb1, tb2, tb3, tb4, half, partsm, dt);

    if (threadIdx.x < MR) {
        const int d = half * MR + threadIdx.x;
        out[b * ND + d] = (x[b * ND + d] - dt[threadIdx.x]) * __expf(-ds[threadIdx.x]);
    }
}

extern "C" void kernel_launch(void* const* d_in, const int* in_sizes, int n_in,
                              void* d_out, int out_size) {
    (void)in_sizes; (void)n_in; (void)out_size;
    const float* x   = (const float*)d_in[0];
    const float* kp  = (const float*)d_in[1];
    const float* sW1 = (const float*)d_in[2];
    const float* sb1 = (const float*)d_in[3];
    const float* sW2 = (const float*)d_in[4];
    const float* sb2 = (const float*)d_in[5];
    const float* sW3 = (const float*)d_in[6];
    const float* sb3 = (const float*)d_in[7];
    const float* sW4 = (const float*)d_in[8];
    const float* sb4 = (const float*)d_in[9];
    const float* tW1 = (const float*)d_in[10];
    const float* tb1 = (const float*)d_in[11];
    const float* tW2 = (const float*)d_in[12];
    const float* tb2 = (const float*)d_in[13];
    const float* tW3 = (const float*)d_in[14];
    const float* tb3 = (const float*)d_in[15];
    const float* tW4 = (const float*)d_in[16];
    const float* tb4 = (const float*)d_in[17];
    float* out = (float*)d_out;

    convert_kernel<<<(NH * NH / 2 + 255) / 256, 256>>>(sW1, sW2, sW3, sW4, tW1, tW2, tW3, tW4);

    cudaFuncSetAttribute(decoder_kernel, cudaFuncAttributeMaxDynamicSharedMemorySize, SMEM_BYTES);
    decoder_kernel<<<NB * 2, 256, SMEM_BYTES>>>(x, kp,
                                                sb1, sb2, sb3, sb4,
                                                tb1, tb2, tb3, tb4,
                                                out);
}